// round 2
// baseline (speedup 1.0000x reference)
#include <cuda_runtime.h>
#include <cuda_bf16.h>

// Problem constants (fixed by reference: B=2, S=2048, D=1024, H=16, Dk=64)
#define BB 2
#define SS 2048
#define DM 1024
#define HH 16
#define DK 64

// Scratch: Q,K,V in [B,H,S,Dk], ctx in [B,S,D]. Static device arrays (allowed).
__device__ float g_Q[BB * HH * SS * DK];
__device__ float g_K[BB * HH * SS * DK];
__device__ float g_V[BB * HH * SS * DK];
__device__ float g_ctx[BB * SS * DM];

// ----------------------------------------------------------------------------
// GEMM: out[m,n] = sum_k A[m,k] * W[n,k] + bias[n]
// A: [M,K] row-major (M=4096, K=1024), W: [N,K] row-major (N=1024).
// mode 1/2/3: scatter into g_Q/g_K/g_V as [B,H,S,Dk] (m=(b,s), n=(h,dk)).
// mode 0:     A is ignored, source is g_ctx; write C row-major [M,N].
// Tile 128x128x8, 256 threads, 8x8 microtile per thread.
// ----------------------------------------------------------------------------
__global__ __launch_bounds__(256) void gemm_xwT_kernel(
    const float* __restrict__ A, const float* __restrict__ W,
    const float* __restrict__ bias, float* __restrict__ C, int mode)
{
    const int K = DM;
    const int N = DM;

    if (mode == 0) A = g_ctx;   // output projection reads ctx scratch

    __shared__ float As[8][128];
    __shared__ float Bs[8][128];

    const int tid = threadIdx.x;
    const int tx = tid & 15;        // 0..15 -> 8 cols each
    const int ty = tid >> 4;        // 0..15 -> 8 rows each
    const int m0 = blockIdx.y * 128;
    const int n0 = blockIdx.x * 128;

    const int lr = tid >> 1;        // 0..127: row within tile for loads
    const int lc = (tid & 1) * 4;   // 0 or 4: k offset for float4 load

    const float* Aptr = A + (long)(m0 + lr) * K + lc;
    const float* Wptr = W + (long)(n0 + lr) * K + lc;

    float acc[8][8];
#pragma unroll
    for (int i = 0; i < 8; i++)
#pragma unroll
        for (int j = 0; j < 8; j++) acc[i][j] = 0.f;

    for (int k0 = 0; k0 < K; k0 += 8) {
        float4 a4 = *(const float4*)(Aptr + k0);
        float4 b4 = *(const float4*)(Wptr + k0);

        __syncthreads();
        As[lc + 0][lr] = a4.x; As[lc + 1][lr] = a4.y;
        As[lc + 2][lr] = a4.z; As[lc + 3][lr] = a4.w;
        Bs[lc + 0][lr] = b4.x; Bs[lc + 1][lr] = b4.y;
        Bs[lc + 2][lr] = b4.z; Bs[lc + 3][lr] = b4.w;
        __syncthreads();

#pragma unroll
        for (int kk = 0; kk < 8; kk++) {
            float a[8], b[8];
            ((float4*)a)[0] = *(const float4*)&As[kk][ty * 8];
            ((float4*)a)[1] = *(const float4*)&As[kk][ty * 8 + 4];
            ((float4*)b)[0] = *(const float4*)&Bs[kk][tx * 8];
            ((float4*)b)[1] = *(const float4*)&Bs[kk][tx * 8 + 4];
#pragma unroll
            for (int i = 0; i < 8; i++)
#pragma unroll
                for (int j = 0; j < 8; j++)
                    acc[i][j] = fmaf(a[i], b[j], acc[i][j]);
        }
    }

    // Select destination
    float* dstQKV = (mode == 1) ? g_Q : (mode == 2) ? g_K : g_V;

#pragma unroll
    for (int i = 0; i < 8; i++) {
        const int m = m0 + ty * 8 + i;
#pragma unroll
        for (int j = 0; j < 8; j++) {
            const int n = n0 + tx * 8 + j;
            const float v = acc[i][j] + bias[n];
            if (mode == 0) {
                C[(long)m * N + n] = v;
            } else {
                const int b = m >> 11;       // m / 2048
                const int s = m & 2047;
                const int h = n >> 6;        // n / 64
                const int dk = n & 63;
                dstQKV[(((long)(b * HH + h) * SS) + s) * DK + dk] = v;
            }
        }
    }
}

// ----------------------------------------------------------------------------
// Flash-style attention. One CTA per (b, h, 128-query tile). 128 threads,
// one thread per query row. q and o accumulators in registers; K/V chunks of
// 32 rows staged in smem, read as broadcast float4.
// scores scaled by 1/sqrt(Dk) = 0.125; softmax over all 2048 keys.
// Writes g_ctx [B,S,D] with d = h*64 + dk.
// ----------------------------------------------------------------------------
__global__ __launch_bounds__(128) void attn_kernel()
{
    __shared__ float ks[32][64];
    __shared__ float vs[32][64];

    const int tid = threadIdx.x;
    const int qt = blockIdx.x;   // 0..15
    const int h  = blockIdx.y;   // 0..15
    const int b  = blockIdx.z;   // 0..1

    const long bh = ((long)(b * HH + h)) * SS * DK;
    const float* Qp = g_Q + bh;
    const float* Kp = g_K + bh;
    const float* Vp = g_V + bh;

    const int s = qt * 128 + tid;

    float q[DK];
#pragma unroll
    for (int d = 0; d < DK; d += 4) {
        float4 t = *(const float4*)(Qp + (long)s * DK + d);
        q[d] = t.x; q[d + 1] = t.y; q[d + 2] = t.z; q[d + 3] = t.w;
    }

    float o[DK];
#pragma unroll
    for (int d = 0; d < DK; d++) o[d] = 0.f;
    float mrun = -1e30f;
    float lrun = 0.f;
    const float scale = 0.125f;

    for (int kt = 0; kt < SS; kt += 32) {
        __syncthreads();
        // Load 32x64 K and V tiles: 512 float4 each, 128 threads -> 4 float4 each.
#pragma unroll
        for (int i = 0; i < 4; i++) {
            const int idx = tid + i * 128;        // float4 index 0..511
            const int j = idx >> 4;               // key row 0..31
            const int d4 = (idx & 15) * 4;        // dim offset
            *(float4*)&ks[j][d4] = *(const float4*)(Kp + (long)(kt + j) * DK + d4);
            *(float4*)&vs[j][d4] = *(const float4*)(Vp + (long)(kt + j) * DK + d4);
        }
        __syncthreads();

        float sc[32];
        float mnew = mrun;
#pragma unroll
        for (int j = 0; j < 32; j++) {
            float acc = 0.f;
#pragma unroll
            for (int d = 0; d < DK; d += 4) {
                float4 kk = *(const float4*)&ks[j][d];
                acc = fmaf(q[d], kk.x, acc);
                acc = fmaf(q[d + 1], kk.y, acc);
                acc = fmaf(q[d + 2], kk.z, acc);
                acc = fmaf(q[d + 3], kk.w, acc);
            }
            sc[j] = acc * scale;
            mnew = fmaxf(mnew, sc[j]);
        }

        const float corr = __expf(mrun - mnew);
        mrun = mnew;
        lrun *= corr;
#pragma unroll
        for (int d = 0; d < DK; d++) o[d] *= corr;

#pragma unroll
        for (int j = 0; j < 32; j++) {
            const float p = __expf(sc[j] - mrun);
            lrun += p;
#pragma unroll
            for (int d = 0; d < DK; d += 4) {
                float4 vv = *(const float4*)&vs[j][d];
                o[d]     = fmaf(p, vv.x, o[d]);
                o[d + 1] = fmaf(p, vv.y, o[d + 1]);
                o[d + 2] = fmaf(p, vv.z, o[d + 2]);
                o[d + 3] = fmaf(p, vv.w, o[d + 3]);
            }
        }
    }

    const float inv = 1.f / lrun;
    float* op = g_ctx + ((long)(b * SS + s)) * DM + h * DK;
#pragma unroll
    for (int d = 0; d < DK; d += 4) {
        float4 t;
        t.x = o[d] * inv; t.y = o[d + 1] * inv;
        t.z = o[d + 2] * inv; t.w = o[d + 3] * inv;
        *(float4*)(op + d) = t;
    }
}

// ----------------------------------------------------------------------------
// kernel_launch: kernel launches ONLY (no runtime API calls at all), so graph
// capture is trivially safe.
// ----------------------------------------------------------------------------
extern "C" void kernel_launch(void* const* d_in, const int* in_sizes, int n_in,
                              void* d_out, int out_size)
{
    const float* q   = (const float*)d_in[0];
    const float* k   = (const float*)d_in[1];
    const float* v   = (const float*)d_in[2];
    const float* w_q = (const float*)d_in[3];
    const float* b_q = (const float*)d_in[4];
    const float* w_k = (const float*)d_in[5];
    const float* b_k = (const float*)d_in[6];
    const float* w_v = (const float*)d_in[7];
    const float* b_v = (const float*)d_in[8];
    const float* w_o = (const float*)d_in[9];
    const float* b_o = (const float*)d_in[10];

    dim3 gblk(256);
    dim3 ggrid(DM / 128, (BB * SS) / 128);   // 8 x 32

    gemm_xwT_kernel<<<ggrid, gblk>>>(q, w_q, b_q, nullptr, 1);
    gemm_xwT_kernel<<<ggrid, gblk>>>(k, w_k, b_k, nullptr, 2);
    gemm_xwT_kernel<<<ggrid, gblk>>>(v, w_v, b_v, nullptr, 3);

    attn_kernel<<<dim3(SS / 128, HH, BB), 128>>>();

    gemm_xwT_kernel<<<ggrid, gblk>>>(nullptr, w_o, b_o, (float*)d_out, 0);
}

// round 4
// speedup vs baseline: 2.7780x; 2.7780x over previous
#include <cuda_runtime.h>
#include <cuda_bf16.h>
#include <cstdint>

// Problem constants (fixed: B=2, S=2048, D=1024, H=16, Dk=64)
#define BB 2
#define SS 2048
#define DM 1024
#define HH 16
#define DK 64

// Scratch (static device arrays — allowed)
__device__ float g_Q[BB * HH * SS * DK];
__device__ float g_K[BB * HH * SS * DK];
__device__ float g_V[BB * HH * SS * DK];
__device__ float g_ctx[BB * SS * DM];

// ============================================================================
// Warp-level bf16 MMA (sm_80+ baseline ISA; works at plain sm_100 target)
// D(16x8,f32) += A(16x16,bf16,row) * B(16x8,bf16,col)
// ============================================================================
__device__ __forceinline__ void mma_bf16(float* d, const uint32_t* a, const uint32_t* b) {
    asm volatile(
        "mma.sync.aligned.m16n8k16.row.col.f32.bf16.bf16.f32 "
        "{%0,%1,%2,%3}, {%4,%5,%6,%7}, {%8,%9}, {%0,%1,%2,%3};"
        : "+f"(d[0]), "+f"(d[1]), "+f"(d[2]), "+f"(d[3])
        : "r"(a[0]), "r"(a[1]), "r"(a[2]), "r"(a[3]), "r"(b[0]), "r"(b[1]));
}

// Split (x,y) into packed bf16x2 hi and lo-residual words.
__device__ __forceinline__ void hilo2(float x, float y, uint32_t& hi, uint32_t& lo) {
    __nv_bfloat16 hx = __float2bfloat16(x);
    __nv_bfloat16 hy = __float2bfloat16(y);
    __nv_bfloat162 hp(hx, hy);
    hi = *reinterpret_cast<uint32_t*>(&hp);
    __nv_bfloat16 lx = __float2bfloat16(x - __bfloat162float(hx));
    __nv_bfloat16 ly = __float2bfloat16(y - __bfloat162float(hy));
    __nv_bfloat162 lp(lx, ly);
    lo = *reinterpret_cast<uint32_t*>(&lp);
}

// ============================================================================
// GEMM: out[m,n] = sum_k A[m,k]*W[n,k] + bias[n]   (M=4096, N=1024, K=1024)
// CTA tile 128x128, K-chunk 32, 256 threads = 8 warps (4 along M, 2 along N),
// warp tile 32x64. bf16 hi/lo split (3 MMAs per logical MMA).
// Smem row stride = 20 words (16 data + 4 pad): fragment LDS addr = 20g+tg
// is a perfect permutation mod 32 -> conflict-free.
// mode 1/2/3: scatter into g_Q/g_K/g_V [B,H,S,Dk]. mode 0: A:=g_ctx, C row-major.
// ============================================================================
__global__ __launch_bounds__(256) void gemm_tc(
    const float* __restrict__ A, const float* __restrict__ W,
    const float* __restrict__ bias, float* __restrict__ C, int mode)
{
    __shared__ uint32_t sAh[2560], sAl[2560], sWh[2560], sWl[2560];

    const int tid = threadIdx.x;
    const int wid = tid >> 5, lane = tid & 31;
    const int g = lane >> 2, tg = lane & 3;
    const int wm = wid & 3, wn = wid >> 2;
    const int m0 = blockIdx.y * 128, n0 = blockIdx.x * 128;

    if (mode == 0) A = g_ctx;

    float acc[16][4];
#pragma unroll
    for (int t = 0; t < 16; ++t)
#pragma unroll
        for (int i = 0; i < 4; ++i) acc[t][i] = 0.f;

    for (int kc = 0; kc < 32; ++kc) {
        const int k0 = kc * 32;
#pragma unroll
        for (int it = 0; it < 4; ++it) {
            const int idx = tid + it * 256;       // 0..1023
            const int r = idx >> 3;               // row 0..127
            const int c4 = idx & 7;               // float4 within 32-k row
            const float4 a4 = *(const float4*)(A + (m0 + r) * DM + k0 + c4 * 4);
            const float4 w4 = *(const float4*)(W + (n0 + r) * DM + k0 + c4 * 4);
            const int w = r * 20 + c4 * 2;
            uint32_t h0, l0, h1, l1;
            hilo2(a4.x, a4.y, h0, l0); hilo2(a4.z, a4.w, h1, l1);
            sAh[w] = h0; sAh[w + 1] = h1; sAl[w] = l0; sAl[w + 1] = l1;
            hilo2(w4.x, w4.y, h0, l0); hilo2(w4.z, w4.w, h1, l1);
            sWh[w] = h0; sWh[w + 1] = h1; sWl[w] = l0; sWl[w + 1] = l1;
        }
        __syncthreads();

#pragma unroll
        for (int ks = 0; ks < 2; ++ks) {
            uint32_t ah[2][4], al[2][4], bh[8][2], bl[8][2];
#pragma unroll
            for (int mt = 0; mt < 2; ++mt) {
                const int w0 = (wm * 32 + mt * 16 + g) * 20 + ks * 8 + tg;
                ah[mt][0] = sAh[w0];       ah[mt][1] = sAh[w0 + 160];
                ah[mt][2] = sAh[w0 + 4];   ah[mt][3] = sAh[w0 + 164];
                al[mt][0] = sAl[w0];       al[mt][1] = sAl[w0 + 160];
                al[mt][2] = sAl[w0 + 4];   al[mt][3] = sAl[w0 + 164];
            }
#pragma unroll
            for (int nt = 0; nt < 8; ++nt) {
                const int w0 = (wn * 64 + nt * 8 + g) * 20 + ks * 8 + tg;
                bh[nt][0] = sWh[w0]; bh[nt][1] = sWh[w0 + 4];
                bl[nt][0] = sWl[w0]; bl[nt][1] = sWl[w0 + 4];
            }
#pragma unroll
            for (int mt = 0; mt < 2; ++mt)
#pragma unroll
                for (int nt = 0; nt < 8; ++nt) {
                    float* d = acc[mt * 8 + nt];
                    mma_bf16(d, ah[mt], bh[nt]);
                    mma_bf16(d, ah[mt], bl[nt]);
                    mma_bf16(d, al[mt], bh[nt]);
                }
        }
        __syncthreads();
    }

    // Epilogue: acc layout c0=(g,2tg) c1=(g,2tg+1) c2=(g+8,2tg) c3=(g+8,2tg+1)
    float* dstQKV = (mode == 1) ? g_Q : (mode == 2) ? g_K : g_V;
#pragma unroll
    for (int mt = 0; mt < 2; ++mt) {
        const int r0 = m0 + wm * 32 + mt * 16 + g;
        const int r1 = r0 + 8;
#pragma unroll
        for (int nt = 0; nt < 8; ++nt) {
            const float* d = acc[mt * 8 + nt];
            const int col = n0 + wn * 64 + nt * 8 + 2 * tg;
            const float bv0 = bias[col], bv1 = bias[col + 1];
            if (mode == 0) {
                *(float2*)(C + (size_t)r0 * DM + col) = make_float2(d[0] + bv0, d[1] + bv1);
                *(float2*)(C + (size_t)r1 * DM + col) = make_float2(d[2] + bv0, d[3] + bv1);
            } else {
                const int hh = col >> 6, dk = col & 63;    // pair stays in one head
                const int b0_ = r0 >> 11, s0_ = r0 & 2047;
                const int b1_ = r1 >> 11, s1_ = r1 & 2047;
                *(float2*)(dstQKV + (((size_t)(b0_ * HH + hh) * SS) + s0_) * DK + dk)
                    = make_float2(d[0] + bv0, d[1] + bv1);
                *(float2*)(dstQKV + (((size_t)(b1_ * HH + hh) * SS) + s1_) * DK + dk)
                    = make_float2(d[2] + bv0, d[3] + bv1);
            }
        }
    }
}

// ============================================================================
// Flash attention with warp MMAs. 1 CTA per (b,h,128-query tile); 8 warps,
// each owns 16 query rows. K-tile 64 keys/iter.
// K smem: [key][dk] bf16 hi/lo, stride 36 words. V smem: transposed [dk][key],
// stride 36 words. Fragment LDS addr = 36g+tg+... -> 4g+tg mod 32: perfect.
// P fragments built directly from S accumulators (layout identity).
// ============================================================================
__global__ __launch_bounds__(256) void attn_tc()
{
    __shared__ uint32_t sKh[2304], sKl[2304], sVh[2304], sVl[2304];

    const int tid = threadIdx.x;
    const int wid = tid >> 5, lane = tid & 31;
    const int g = lane >> 2, tg = lane & 3;
    const int qt = blockIdx.x, h = blockIdx.y, b = blockIdx.z;

    const size_t bh = (size_t)(b * HH + h) * SS * DK;
    const float* Qp = g_Q + bh;
    const float* Kp = g_K + bh;
    const float* Vp = g_V + bh;
    const int q0 = qt * 128 + wid * 16;

    // Q fragments (per warp, resident): a0=(g,klo) a1=(g+8,klo) a2=(g,k+8) a3=(g+8,k+8)
    uint32_t qh[4][4], ql[4][4];
#pragma unroll
    for (int ks = 0; ks < 4; ++ks) {
#pragma unroll
        for (int half = 0; half < 2; ++half) {
            const int dd = ks * 16 + 2 * tg + half * 8;
            const float2 x0 = *(const float2*)(Qp + (size_t)(q0 + g) * DK + dd);
            const float2 x1 = *(const float2*)(Qp + (size_t)(q0 + g + 8) * DK + dd);
            hilo2(x0.x, x0.y, qh[ks][half * 2 + 0], ql[ks][half * 2 + 0]);
            hilo2(x1.x, x1.y, qh[ks][half * 2 + 1], ql[ks][half * 2 + 1]);
        }
    }

    float O[8][4];
#pragma unroll
    for (int nt = 0; nt < 8; ++nt)
#pragma unroll
        for (int i = 0; i < 4; ++i) O[nt][i] = 0.f;
    float m0r = -1e30f, m1r = -1e30f, l0r = 0.f, l1r = 0.f;
    const float scale = 0.125f;   // 1/sqrt(64)

    for (int kt = 0; kt < 32; ++kt) {
        const float* Kt = Kp + (size_t)kt * 64 * DK;
        const float* Vt = Vp + (size_t)kt * 64 * DK;
        __syncthreads();
        // K tile: [key r][dk] -> bf16 hi/lo
#pragma unroll
        for (int it = 0; it < 4; ++it) {
            const int idx = tid + it * 256;
            const int r = idx >> 4, c4 = idx & 15;
            const float4 k4 = *(const float4*)(Kt + r * DK + c4 * 4);
            uint32_t h0, l0, h1, l1;
            hilo2(k4.x, k4.y, h0, l0); hilo2(k4.z, k4.w, h1, l1);
            const int w = r * 36 + c4 * 2;
            sKh[w] = h0; sKh[w + 1] = h1; sKl[w] = l0; sKl[w + 1] = l1;
        }
        // V tile transposed: word (dk, keypair r) = pack(V[2r][dk], V[2r+1][dk])
#pragma unroll
        for (int it = 0; it < 4; ++it) {
            const int idx = tid + it * 256;
            const int r = idx >> 5;    // keypair 0..31
            const int c = idx & 31;    // dk pair 0..31
            const float2 v0 = *(const float2*)(Vt + (2 * r) * DK + 2 * c);
            const float2 v1 = *(const float2*)(Vt + (2 * r + 1) * DK + 2 * c);
            uint32_t h0, l0, h1, l1;
            hilo2(v0.x, v1.x, h0, l0);
            hilo2(v0.y, v1.y, h1, l1);
            sVh[(2 * c) * 36 + r] = h0;     sVl[(2 * c) * 36 + r] = l0;
            sVh[(2 * c + 1) * 36 + r] = h1; sVl[(2 * c + 1) * 36 + r] = l1;
        }
        __syncthreads();

        // S = Q K^T (raw, scale applied inside exp)
        float S[8][4];
#pragma unroll
        for (int nt = 0; nt < 8; ++nt)
#pragma unroll
            for (int i = 0; i < 4; ++i) S[nt][i] = 0.f;
#pragma unroll
        for (int ks = 0; ks < 4; ++ks) {
#pragma unroll
            for (int nt = 0; nt < 8; ++nt) {
                const int w0 = (nt * 8 + g) * 36 + ks * 8 + tg;
                uint32_t bhf[2] = { sKh[w0], sKh[w0 + 4] };
                uint32_t blf[2] = { sKl[w0], sKl[w0 + 4] };
                mma_bf16(S[nt], qh[ks], bhf);
                mma_bf16(S[nt], qh[ks], blf);
                mma_bf16(S[nt], ql[ks], bhf);
            }
        }

        // Online softmax (rows g and g+8; quad lanes share rows)
        float mx0 = m0r, mx1 = m1r;
#pragma unroll
        for (int nt = 0; nt < 8; ++nt) {
            mx0 = fmaxf(mx0, fmaxf(S[nt][0], S[nt][1]));
            mx1 = fmaxf(mx1, fmaxf(S[nt][2], S[nt][3]));
        }
        mx0 = fmaxf(mx0, __shfl_xor_sync(0xFFFFFFFFu, mx0, 1));
        mx0 = fmaxf(mx0, __shfl_xor_sync(0xFFFFFFFFu, mx0, 2));
        mx1 = fmaxf(mx1, __shfl_xor_sync(0xFFFFFFFFu, mx1, 1));
        mx1 = fmaxf(mx1, __shfl_xor_sync(0xFFFFFFFFu, mx1, 2));
        const float corr0 = __expf(scale * (m0r - mx0));
        const float corr1 = __expf(scale * (m1r - mx1));
        m0r = mx0; m1r = mx1;

        float sum0 = 0.f, sum1 = 0.f;
        uint32_t ph0[8], pl0[8], ph1[8], pl1[8];
#pragma unroll
        for (int nt = 0; nt < 8; ++nt) {
            const float p0 = __expf(scale * (S[nt][0] - mx0));
            const float p1 = __expf(scale * (S[nt][1] - mx0));
            const float p2 = __expf(scale * (S[nt][2] - mx1));
            const float p3 = __expf(scale * (S[nt][3] - mx1));
            sum0 += p0 + p1; sum1 += p2 + p3;
            hilo2(p0, p1, ph0[nt], pl0[nt]);
            hilo2(p2, p3, ph1[nt], pl1[nt]);
        }
        sum0 += __shfl_xor_sync(0xFFFFFFFFu, sum0, 1);
        sum0 += __shfl_xor_sync(0xFFFFFFFFu, sum0, 2);
        sum1 += __shfl_xor_sync(0xFFFFFFFFu, sum1, 1);
        sum1 += __shfl_xor_sync(0xFFFFFFFFu, sum1, 2);
        l0r = l0r * corr0 + sum0;
        l1r = l1r * corr1 + sum1;
#pragma unroll
        for (int nt = 0; nt < 8; ++nt) {
            O[nt][0] *= corr0; O[nt][1] *= corr0;
            O[nt][2] *= corr1; O[nt][3] *= corr1;
        }

        // O += P V   (A-frags are S/P fragments: identity layout)
#pragma unroll
        for (int kk = 0; kk < 4; ++kk) {
            uint32_t ah[4] = { ph0[2 * kk], ph1[2 * kk], ph0[2 * kk + 1], ph1[2 * kk + 1] };
            uint32_t al[4] = { pl0[2 * kk], pl1[2 * kk], pl0[2 * kk + 1], pl1[2 * kk + 1] };
#pragma unroll
            for (int nt = 0; nt < 8; ++nt) {
                const int w0 = (nt * 8 + g) * 36 + kk * 8 + tg;
                uint32_t bhf[2] = { sVh[w0], sVh[w0 + 4] };
                uint32_t blf[2] = { sVl[w0], sVl[w0 + 4] };
                mma_bf16(O[nt], ah, bhf);
                mma_bf16(O[nt], ah, blf);
                mma_bf16(O[nt], al, bhf);
            }
        }
    }

    // Epilogue
    const float inv0 = 1.f / l0r, inv1 = 1.f / l1r;
    const int r0 = q0 + g, r1 = q0 + g + 8;
    float* base0 = g_ctx + ((size_t)(b * SS + r0)) * DM + h * DK;
    float* base1 = g_ctx + ((size_t)(b * SS + r1)) * DM + h * DK;
#pragma unroll
    for (int nt = 0; nt < 8; ++nt) {
        const int dk = nt * 8 + 2 * tg;
        *(float2*)(base0 + dk) = make_float2(O[nt][0] * inv0, O[nt][1] * inv0);
        *(float2*)(base1 + dk) = make_float2(O[nt][2] * inv1, O[nt][3] * inv1);
    }
}

// ----------------------------------------------------------------------------
extern "C" void kernel_launch(void* const* d_in, const int* in_sizes, int n_in,
                              void* d_out, int out_size)
{
    const float* q   = (const float*)d_in[0];
    const float* k   = (const float*)d_in[1];
    const float* v   = (const float*)d_in[2];
    const float* w_q = (const float*)d_in[3];
    const float* b_q = (const float*)d_in[4];
    const float* w_k = (const float*)d_in[5];
    const float* b_k = (const float*)d_in[6];
    const float* w_v = (const float*)d_in[7];
    const float* b_v = (const float*)d_in[8];
    const float* w_o = (const float*)d_in[9];
    const float* b_o = (const float*)d_in[10];

    dim3 gblk(256);
    dim3 ggrid(DM / 128, (BB * SS) / 128);   // 8 x 32

    gemm_tc<<<ggrid, gblk>>>(q, w_q, b_q, nullptr, 1);
    gemm_tc<<<ggrid, gblk>>>(k, w_k, b_k, nullptr, 2);
    gemm_tc<<<ggrid, gblk>>>(v, w_v, b_v, nullptr, 3);

    attn_tc<<<dim3(SS / 128, HH, BB), 256>>>();

    gemm_tc<<<ggrid, gblk>>>(nullptr, w_o, b_o, (float*)d_out, 0);
}

// round 8
// speedup vs baseline: 2.8534x; 1.0272x over previous
#include <cuda_runtime.h>
#include <cuda_bf16.h>
#include <cstdint>

// Problem constants (fixed: B=2, S=2048, D=1024, H=16, Dk=64)
#define BB 2
#define SS 2048
#define DM 1024
#define HH 16
#define DK 64
#define NTOK (BB * SS)          // 4096 rows
#define NEL  (NTOK * DM)        // 4,194,304

// ---------------- static device scratch: 64 MB total (proven-safe) --------
// Q,K: [B,H,S,Dk] hi/lo ; V transposed: [B,H,Dk,S] hi/lo  (48 MB)
__device__ __nv_bfloat16 g_Qh[NEL], g_Ql[NEL];
__device__ __nv_bfloat16 g_Kh[NEL], g_Kl[NEL];
__device__ __nv_bfloat16 g_Vth[NEL], g_Vtl[NEL];
// ctx [B,S,DM] fp32 (16 MB)
__device__ float g_ctx[NEL];

// ---------------- helpers ----------------
__device__ __forceinline__ uint32_t smem_u32(const void* p) {
    uint32_t a;
    asm("{ .reg .u64 t; cvta.to.shared.u64 t, %1; cvt.u32.u64 %0, t; }"
        : "=r"(a) : "l"(p));
    return a;
}

__device__ __forceinline__ void mma_bf16(float* d, const uint32_t* a, const uint32_t* b) {
    asm volatile(
        "mma.sync.aligned.m16n8k16.row.col.f32.bf16.bf16.f32 "
        "{%0,%1,%2,%3}, {%4,%5,%6,%7}, {%8,%9}, {%0,%1,%2,%3};"
        : "+f"(d[0]), "+f"(d[1]), "+f"(d[2]), "+f"(d[3])
        : "r"(a[0]), "r"(a[1]), "r"(a[2]), "r"(a[3]), "r"(b[0]), "r"(b[1]));
}

__device__ __forceinline__ void hilo2(float x, float y, uint32_t& hi, uint32_t& lo) {
    __nv_bfloat16 hx = __float2bfloat16(x);
    __nv_bfloat16 hy = __float2bfloat16(y);
    __nv_bfloat162 hp(hx, hy);
    hi = *reinterpret_cast<uint32_t*>(&hp);
    __nv_bfloat16 lx = __float2bfloat16(x - __bfloat162float(hx));
    __nv_bfloat16 ly = __float2bfloat16(y - __bfloat162float(hy));
    __nv_bfloat162 lp(lx, ly);
    lo = *reinterpret_cast<uint32_t*>(&lp);
}

__device__ __forceinline__ void store_hilo(__nv_bfloat16* h, __nv_bfloat16* l,
                                           size_t idx, float v) {
    __nv_bfloat16 hb = __float2bfloat16(v);
    h[idx] = hb;
    l[idx] = __float2bfloat16(v - __bfloat162float(hb));
}

#define CPA16(dst, src) \
    asm volatile("cp.async.cg.shared.global [%0], [%1], 16;" \
                 :: "r"(dst), "l"(src) : "memory")
#define CPA_COMMIT() asm volatile("cp.async.commit_group;" ::: "memory")
#define CPA_WAIT1()  asm volatile("cp.async.wait_group 1;" ::: "memory")
#define CPA_WAIT0()  asm volatile("cp.async.wait_group 0;" ::: "memory")

// ============================================================================
// GEMM: out[m,n] = sum_k A[m,k]*W[n,k] + bias[n]  (M=4096, N=1024, K=1024)
// fp32 sources, inline bf16 hi/lo conversion in the smem fill, register-staged
// prefetch of the next k-chunk overlapping the MMA section.
// CTA 128x128, K-chunk 32, 32KB static smem (single stage).
// Smem row: 128B = 8 x 16B chunks (0-3 hi cols 0..31, 4-7 lo), swizzle
// p = c ^ (r&7) -> every fragment LDS is a perfect 32-bank permutation.
// mode 1/2: Q/K hi/lo [B,H,S,Dk]; mode 3: Vt hi/lo [B,H,Dk,S]; mode 0: fp32 C
// with A := g_ctx.
// ============================================================================
__global__ __launch_bounds__(256) void gemm_tc(
    const float* __restrict__ A, const float* __restrict__ W,
    const float* __restrict__ bias, float* __restrict__ C, int mode)
{
    __shared__ uint32_t sg[8192];            // 32KB: A 4096w | W 4096w
    const int tid = threadIdx.x;
    const int wid = tid >> 5, lane = tid & 31;
    const int g = lane >> 2, tg = lane & 3;
    const int wm = wid & 3, wn = wid >> 2;
    const int m0 = blockIdx.y * 128, n0 = blockIdx.x * 128;

    if (mode == 0) A = g_ctx;

    // loader: thread owns row r (2 threads/row), cols half*16..+15
    const int lr = tid >> 1, half = tid & 1;
    const float* pA = A + (size_t)(m0 + lr) * DM + half * 16;
    const float* pW = W + (size_t)(n0 + lr) * DM + half * 16;
    // STS byte offsets for the 4 chunks this thread writes per matrix
    const int rsw = lr & 7;
    const uint32_t stA0 = lr * 128 + (((half * 2)     ^ rsw) << 4);
    const uint32_t stA1 = lr * 128 + (((half * 2 + 1) ^ rsw) << 4);
    const uint32_t stA2 = lr * 128 + (((half * 2 + 4) ^ rsw) << 4);
    const uint32_t stA3 = lr * 128 + (((half * 2 + 5) ^ rsw) << 4);

    float4 a4[4], w4[4];
#pragma unroll
    for (int j = 0; j < 4; ++j) {
        a4[j] = *(const float4*)(pA + j * 4);
        w4[j] = *(const float4*)(pW + j * 4);
    }

    float acc[16][4];
#pragma unroll
    for (int t = 0; t < 16; ++t)
#pragma unroll
        for (int i = 0; i < 4; ++i) acc[t][i] = 0.f;

    char* sb = (char*)sg;

    for (int kc = 0; kc < 32; ++kc) {
        // convert + STS current chunk
        {
            uint4 hi0, hi1, lo0, lo1;
            hilo2(a4[0].x, a4[0].y, hi0.x, lo0.x); hilo2(a4[0].z, a4[0].w, hi0.y, lo0.y);
            hilo2(a4[1].x, a4[1].y, hi0.z, lo0.z); hilo2(a4[1].z, a4[1].w, hi0.w, lo0.w);
            hilo2(a4[2].x, a4[2].y, hi1.x, lo1.x); hilo2(a4[2].z, a4[2].w, hi1.y, lo1.y);
            hilo2(a4[3].x, a4[3].y, hi1.z, lo1.z); hilo2(a4[3].z, a4[3].w, hi1.w, lo1.w);
            *(uint4*)(sb + stA0) = hi0; *(uint4*)(sb + stA1) = hi1;
            *(uint4*)(sb + stA2) = lo0; *(uint4*)(sb + stA3) = lo1;
            hilo2(w4[0].x, w4[0].y, hi0.x, lo0.x); hilo2(w4[0].z, w4[0].w, hi0.y, lo0.y);
            hilo2(w4[1].x, w4[1].y, hi0.z, lo0.z); hilo2(w4[1].z, w4[1].w, hi0.w, lo0.w);
            hilo2(w4[2].x, w4[2].y, hi1.x, lo1.x); hilo2(w4[2].z, w4[2].w, hi1.y, lo1.y);
            hilo2(w4[3].x, w4[3].y, hi1.z, lo1.z); hilo2(w4[3].z, w4[3].w, hi1.w, lo1.w);
            *(uint4*)(sb + 16384 + stA0) = hi0; *(uint4*)(sb + 16384 + stA1) = hi1;
            *(uint4*)(sb + 16384 + stA2) = lo0; *(uint4*)(sb + 16384 + stA3) = lo1;
        }
        __syncthreads();

        // prefetch next chunk into regs (overlaps MMA section)
        if (kc < 31) {
            const int ko = (kc + 1) * 32;
#pragma unroll
            for (int j = 0; j < 4; ++j) {
                a4[j] = *(const float4*)(pA + ko + j * 4);
                w4[j] = *(const float4*)(pW + ko + j * 4);
            }
        }

        const uint32_t* sA = sg;
        const uint32_t* sW = sg + 4096;
#pragma unroll
        for (int ks = 0; ks < 2; ++ks) {
            const int oH0 = (((2 * ks)     ^ g) << 2) + tg;
            const int oH1 = (((2 * ks + 1) ^ g) << 2) + tg;
            const int oL0 = (((2 * ks + 4) ^ g) << 2) + tg;
            const int oL1 = (((2 * ks + 5) ^ g) << 2) + tg;
            uint32_t ah[2][4], al[2][4];
#pragma unroll
            for (int mt = 0; mt < 2; ++mt) {
                const int rb = (wm * 32 + mt * 16 + g) * 32;
                ah[mt][0] = sA[rb + oH0];       ah[mt][1] = sA[rb + 256 + oH0];
                ah[mt][2] = sA[rb + oH1];       ah[mt][3] = sA[rb + 256 + oH1];
                al[mt][0] = sA[rb + oL0];       al[mt][1] = sA[rb + 256 + oL0];
                al[mt][2] = sA[rb + oL1];       al[mt][3] = sA[rb + 256 + oL1];
            }
#pragma unroll
            for (int nt = 0; nt < 8; ++nt) {
                const int rb = (wn * 64 + nt * 8 + g) * 32;
                uint32_t bh[2] = { sW[rb + oH0], sW[rb + oH1] };
                uint32_t bl[2] = { sW[rb + oL0], sW[rb + oL1] };
#pragma unroll
                for (int mt = 0; mt < 2; ++mt) {
                    float* d = acc[mt * 8 + nt];
                    mma_bf16(d, ah[mt], bh);
                    mma_bf16(d, ah[mt], bl);
                    mma_bf16(d, al[mt], bh);
                }
            }
        }
        __syncthreads();
    }

    // Epilogue: acc c0=(g,2tg) c1=(g,2tg+1) c2=(g+8,2tg) c3=(g+8,2tg+1)
#pragma unroll
    for (int mt = 0; mt < 2; ++mt) {
        const int rr0 = m0 + wm * 32 + mt * 16 + g;
        const int rr1 = rr0 + 8;
        const int b0_ = rr0 >> 11, s0_ = rr0 & 2047;
        const int b1_ = rr1 >> 11, s1_ = rr1 & 2047;
#pragma unroll
        for (int nt = 0; nt < 8; ++nt) {
            const float* d = acc[mt * 8 + nt];
            const int col = n0 + wn * 64 + nt * 8 + 2 * tg;
            const float bv0 = bias[col], bv1 = bias[col + 1];
            const float v0 = d[0] + bv0, v1 = d[1] + bv1;
            const float v2 = d[2] + bv0, v3 = d[3] + bv1;
            if (mode == 0) {
                *(float2*)(C + (size_t)rr0 * DM + col) = make_float2(v0, v1);
                *(float2*)(C + (size_t)rr1 * DM + col) = make_float2(v2, v3);
            } else if (mode == 3) {
                const int hh = col >> 6, dk = col & 63;
                const size_t base0 = ((size_t)(b0_ * HH + hh) * DK + dk) * SS;
                const size_t base1 = ((size_t)(b1_ * HH + hh) * DK + dk) * SS;
                store_hilo(g_Vth, g_Vtl, base0 + s0_, v0);
                store_hilo(g_Vth, g_Vtl, base0 + SS + s0_, v1);
                store_hilo(g_Vth, g_Vtl, base1 + s1_, v2);
                store_hilo(g_Vth, g_Vtl, base1 + SS + s1_, v3);
            } else {
                const int hh = col >> 6, dk = col & 63;
                __nv_bfloat16* dh = (mode == 1) ? g_Qh : g_Kh;
                __nv_bfloat16* dl = (mode == 1) ? g_Ql : g_Kl;
                uint32_t hw, lw;
                const size_t w0 = ((((size_t)(b0_ * HH + hh)) * SS + s0_) * DK + dk) >> 1;
                const size_t w1 = ((((size_t)(b1_ * HH + hh)) * SS + s1_) * DK + dk) >> 1;
                hilo2(v0, v1, hw, lw);
                ((uint32_t*)dh)[w0] = hw; ((uint32_t*)dl)[w0] = lw;
                hilo2(v2, v3, hw, lw);
                ((uint32_t*)dh)[w1] = hw; ((uint32_t*)dl)[w1] = lw;
            }
        }
    }
}

// ============================================================================
// Flash attention, bf16 hi/lo tiles via 2-stage cp.async, 32KB static smem.
// 1 CTA per (b,h,128 queries); 8 warps x 16 query rows; 32-key tiles.
// K tile: 32 rows x 128B (swizzle c^(r&7)). Vt tile: 64 rows x 64B
// (swizzle c^((r>>1)&3)). Epilogue writes fp32 g_ctx.
// ============================================================================
__global__ __launch_bounds__(256) void attn_tc()
{
    __shared__ uint32_t sm[8192];            // 2 stages x (Kh|Kl|Vh|Vl 1K words)
    const uint32_t sbase = smem_u32(sm);

    const int tid = threadIdx.x;
    const int wid = tid >> 5, lane = tid & 31;
    const int g = lane >> 2, tg = lane & 3;
    const int qt = blockIdx.x, h = blockIdx.y, b = blockIdx.z;

    const size_t bh = (size_t)(b * HH + h) * SS * DK;
    const size_t bhv = (size_t)(b * HH + h) * DK * SS;
    const int q0 = qt * 128 + wid * 16;

    // precomputed loader state
    const int kr = tid >> 3, kcc = tid & 7;          // K: row 0..31, chunk 0..7
    const uint32_t dK = sbase + kr * 128 + (((kcc ^ (kr & 7)) & 7) << 4);
    const __nv_bfloat16* pKh = g_Kh + bh + (size_t)kr * DK + kcc * 8;
    const __nv_bfloat16* pKl = g_Kl + bh + (size_t)kr * DK + kcc * 8;
    const int vr = tid >> 2, vcc = tid & 3;          // V: row 0..63, chunk 0..3
    const uint32_t dV = sbase + 8192 + vr * 64 + (((vcc ^ ((vr >> 1) & 3)) & 3) << 4);
    const __nv_bfloat16* pVh = g_Vth + bhv + (size_t)vr * SS + vcc * 8;
    const __nv_bfloat16* pVl = g_Vtl + bhv + (size_t)vr * SS + vcc * 8;

    // Q fragments resident
    const uint32_t* Qh32 = (const uint32_t*)(g_Qh + bh);
    const uint32_t* Ql32 = (const uint32_t*)(g_Ql + bh);
    uint32_t qh[4][4], ql[4][4];
#pragma unroll
    for (int ks = 0; ks < 4; ++ks) {
        const int c0 = ks * 8 + tg;
        qh[ks][0] = Qh32[(q0 + g) * 32 + c0];
        qh[ks][1] = Qh32[(q0 + g + 8) * 32 + c0];
        qh[ks][2] = Qh32[(q0 + g) * 32 + c0 + 4];
        qh[ks][3] = Qh32[(q0 + g + 8) * 32 + c0 + 4];
        ql[ks][0] = Ql32[(q0 + g) * 32 + c0];
        ql[ks][1] = Ql32[(q0 + g + 8) * 32 + c0];
        ql[ks][2] = Ql32[(q0 + g) * 32 + c0 + 4];
        ql[ks][3] = Ql32[(q0 + g + 8) * 32 + c0 + 4];
    }

    float O[8][4];
#pragma unroll
    for (int nt = 0; nt < 8; ++nt)
#pragma unroll
        for (int i = 0; i < 4; ++i) O[nt][i] = 0.f;
    float m0r = -1e30f, m1r = -1e30f, l0r = 0.f, l1r = 0.f;
    const float scale = 0.125f;

    const int sv = (g >> 1) & 3;   // V fragment swizzle

    // issue tile 0 into stage 0
    CPA16(dK, pKh); CPA16(dK + 4096, pKl);
    CPA16(dV, pVh); CPA16(dV + 4096, pVl);
    CPA_COMMIT();

    for (int kt = 0; kt < 64; ++kt) {
        if (kt < 63) {
            const uint32_t so = ((kt + 1) & 1) ? 16384u : 0u;
            const size_t koK = (size_t)(kt + 1) * 32 * DK;
            const int koV = (kt + 1) * 32;
            CPA16(dK + so, pKh + koK); CPA16(dK + so + 4096, pKl + koK);
            CPA16(dV + so, pVh + koV); CPA16(dV + so + 4096, pVl + koV);
            CPA_COMMIT();
            CPA_WAIT1();
        } else {
            CPA_WAIT0();
        }
        __syncthreads();

        const uint32_t* sKh = sm + (kt & 1) * 4096;
        const uint32_t* sKl = sKh + 1024;
        const uint32_t* sVh = sKh + 2048;
        const uint32_t* sVl = sKh + 3072;

        // S = Q K^T   (4 key sub-tiles of 8)
        float S[4][4];
#pragma unroll
        for (int nt = 0; nt < 4; ++nt)
#pragma unroll
            for (int i = 0; i < 4; ++i) S[nt][i] = 0.f;
#pragma unroll
        for (int ks = 0; ks < 4; ++ks) {
            const int o0 = ((((2 * ks) ^ g) & 7) << 2) + tg;
            const int o1 = ((((2 * ks + 1) ^ g) & 7) << 2) + tg;
#pragma unroll
            for (int nt = 0; nt < 4; ++nt) {
                const int rb = (nt * 8 + g) * 32;
                uint32_t bhf[2] = { sKh[rb + o0], sKh[rb + o1] };
                uint32_t blf[2] = { sKl[rb + o0], sKl[rb + o1] };
                mma_bf16(S[nt], qh[ks], bhf);
                mma_bf16(S[nt], qh[ks], blf);
                mma_bf16(S[nt], ql[ks], bhf);
            }
        }

        // Online softmax (rows g, g+8)
        float mx0 = m0r, mx1 = m1r;
#pragma unroll
        for (int nt = 0; nt < 4; ++nt) {
            mx0 = fmaxf(mx0, fmaxf(S[nt][0], S[nt][1]));
            mx1 = fmaxf(mx1, fmaxf(S[nt][2], S[nt][3]));
        }
        mx0 = fmaxf(mx0, __shfl_xor_sync(0xFFFFFFFFu, mx0, 1));
        mx0 = fmaxf(mx0, __shfl_xor_sync(0xFFFFFFFFu, mx0, 2));
        mx1 = fmaxf(mx1, __shfl_xor_sync(0xFFFFFFFFu, mx1, 1));
        mx1 = fmaxf(mx1, __shfl_xor_sync(0xFFFFFFFFu, mx1, 2));
        const float corr0 = __expf(scale * (m0r - mx0));
        const float corr1 = __expf(scale * (m1r - mx1));
        m0r = mx0; m1r = mx1;

        float sum0 = 0.f, sum1 = 0.f;
        uint32_t ph0[4], pl0[4], ph1[4], pl1[4];
#pragma unroll
        for (int nt = 0; nt < 4; ++nt) {
            const float p0 = __expf(scale * (S[nt][0] - mx0));
            const float p1 = __expf(scale * (S[nt][1] - mx0));
            const float p2 = __expf(scale * (S[nt][2] - mx1));
            const float p3 = __expf(scale * (S[nt][3] - mx1));
            sum0 += p0 + p1; sum1 += p2 + p3;
            hilo2(p0, p1, ph0[nt], pl0[nt]);
            hilo2(p2, p3, ph1[nt], pl1[nt]);
        }
        sum0 += __shfl_xor_sync(0xFFFFFFFFu, sum0, 1);
        sum0 += __shfl_xor_sync(0xFFFFFFFFu, sum0, 2);
        sum1 += __shfl_xor_sync(0xFFFFFFFFu, sum1, 1);
        sum1 += __shfl_xor_sync(0xFFFFFFFFu, sum1, 2);
        l0r = l0r * corr0 + sum0;
        l1r = l1r * corr1 + sum1;
#pragma unroll
        for (int nt = 0; nt < 8; ++nt) {
            O[nt][0] *= corr0; O[nt][1] *= corr0;
            O[nt][2] *= corr1; O[nt][3] *= corr1;
        }

        // O += P V  (2 keypair steps of 16 keys)
#pragma unroll
        for (int kk = 0; kk < 2; ++kk) {
            const int o0 = ((((2 * kk) ^ sv) & 3) << 2) + tg;
            const int o1 = ((((2 * kk + 1) ^ sv) & 3) << 2) + tg;
            uint32_t ah[4] = { ph0[2 * kk], ph1[2 * kk], ph0[2 * kk + 1], ph1[2 * kk + 1] };
            uint32_t al[4] = { pl0[2 * kk], pl1[2 * kk], pl0[2 * kk + 1], pl1[2 * kk + 1] };
#pragma unroll
            for (int nt = 0; nt < 8; ++nt) {
                const int rb = (nt * 8 + g) * 16;
                uint32_t bhf[2] = { sVh[rb + o0], sVh[rb + o1] };
                uint32_t blf[2] = { sVl[rb + o0], sVl[rb + o1] };
                mma_bf16(O[nt], ah, bhf);
                mma_bf16(O[nt], ah, blf);
                mma_bf16(O[nt], al, bhf);
            }
        }
        __syncthreads();
    }

    // Epilogue -> fp32 ctx
    const float inv0 = 1.f / l0r, inv1 = 1.f / l1r;
    const int r0 = q0 + g, r1 = q0 + g + 8;
    float* base0 = g_ctx + ((size_t)(b * SS + r0)) * DM + h * DK;
    float* base1 = g_ctx + ((size_t)(b * SS + r1)) * DM + h * DK;
#pragma unroll
    for (int nt = 0; nt < 8; ++nt) {
        const int dk = nt * 8 + 2 * tg;
        *(float2*)(base0 + dk) = make_float2(O[nt][0] * inv0, O[nt][1] * inv0);
        *(float2*)(base1 + dk) = make_float2(O[nt][2] * inv1, O[nt][3] * inv1);
    }
}

// ----------------------------------------------------------------------------
// kernel_launch: kernel launches ONLY. No runtime API calls of any kind.
// ----------------------------------------------------------------------------
extern "C" void kernel_launch(void* const* d_in, const int* in_sizes, int n_in,
                              void* d_out, int out_size)
{
    const float* q   = (const float*)d_in[0];
    const float* k   = (const float*)d_in[1];
    const float* v   = (const float*)d_in[2];
    const float* w_q = (const float*)d_in[3];
    const float* b_q = (const float*)d_in[4];
    const float* w_k = (const float*)d_in[5];
    const float* b_k = (const float*)d_in[6];
    const float* w_v = (const float*)d_in[7];
    const float* b_v = (const float*)d_in[8];
    const float* w_o = (const float*)d_in[9];
    const float* b_o = (const float*)d_in[10];

    dim3 gblk(256);
    dim3 ggrid(DM / 128, NTOK / 128);   // 8 x 32

    gemm_tc<<<ggrid, gblk>>>(q, w_q, b_q, nullptr, 1);
    gemm_tc<<<ggrid, gblk>>>(k, w_k, b_k, nullptr, 2);
    gemm_tc<<<ggrid, gblk>>>(v, w_v, b_v, nullptr, 3);

    attn_tc<<<dim3(SS / 128, HH, BB), 256>>>();

    gemm_tc<<<ggrid, gblk>>>(nullptr, w_o, b_o, (float*)d_out, 0);
}

// round 10
// speedup vs baseline: 3.0828x; 1.0804x over previous
#include <cuda_runtime.h>
#include <cuda_bf16.h>
#include <cstdint>

// Problem constants (fixed: B=2, S=2048, D=1024, H=16, Dk=64)
#define BB 2
#define SS 2048
#define DM 1024
#define HH 16
#define DK 64
#define NTOK (BB * SS)          // 4096 rows
#define NEL  (NTOK * DM)        // 4,194,304

// ---------------- static device scratch: 64 MB total (proven-safe) --------
// Q,K: [B,H,S,Dk] hi/lo ; V transposed: [B,H,Dk,S] hi/lo  (48 MB)
__device__ __nv_bfloat16 g_Qh[NEL], g_Ql[NEL];
__device__ __nv_bfloat16 g_Kh[NEL], g_Kl[NEL];
__device__ __nv_bfloat16 g_Vth[NEL], g_Vtl[NEL];
// ctx [B,S,DM] bf16 hi/lo (16 MB). ALSO aliased as the staging area for
// converted weights while ctx is dead (GEMMs 1-3): first DM*DM elements.
__device__ __nv_bfloat16 g_Ch[NEL], g_Cl[NEL];
// w_o staging (GEMM 4) aliases g_Kh/g_Kl, which are dead after attention.

// ---------------- helpers ----------------
__device__ __forceinline__ uint32_t smem_u32(const void* p) {
    uint32_t a;
    asm("{ .reg .u64 t; cvta.to.shared.u64 t, %1; cvt.u32.u64 %0, t; }"
        : "=r"(a) : "l"(p));
    return a;
}

__device__ __forceinline__ void mma_bf16(float* d, const uint32_t* a, const uint32_t* b) {
    asm volatile(
        "mma.sync.aligned.m16n8k16.row.col.f32.bf16.bf16.f32 "
        "{%0,%1,%2,%3}, {%4,%5,%6,%7}, {%8,%9}, {%0,%1,%2,%3};"
        : "+f"(d[0]), "+f"(d[1]), "+f"(d[2]), "+f"(d[3])
        : "r"(a[0]), "r"(a[1]), "r"(a[2]), "r"(a[3]), "r"(b[0]), "r"(b[1]));
}

__device__ __forceinline__ void hilo2(float x, float y, uint32_t& hi, uint32_t& lo) {
    __nv_bfloat16 hx = __float2bfloat16(x);
    __nv_bfloat16 hy = __float2bfloat16(y);
    __nv_bfloat162 hp(hx, hy);
    hi = *reinterpret_cast<uint32_t*>(&hp);
    __nv_bfloat16 lx = __float2bfloat16(x - __bfloat162float(hx));
    __nv_bfloat16 ly = __float2bfloat16(y - __bfloat162float(hy));
    __nv_bfloat162 lp(lx, ly);
    lo = *reinterpret_cast<uint32_t*>(&lp);
}

__device__ __forceinline__ void store_hilo(__nv_bfloat16* h, __nv_bfloat16* l,
                                           size_t idx, float v) {
    __nv_bfloat16 hb = __float2bfloat16(v);
    h[idx] = hb;
    l[idx] = __float2bfloat16(v - __bfloat162float(hb));
}

#define CPA16(dst, src) \
    asm volatile("cp.async.cg.shared.global [%0], [%1], 16;" \
                 :: "r"(dst), "l"(src) : "memory")
#define CPA_COMMIT() asm volatile("cp.async.commit_group;" ::: "memory")
#define CPA_WAIT1()  asm volatile("cp.async.wait_group 1;" ::: "memory")
#define CPA_WAIT0()  asm volatile("cp.async.wait_group 0;" ::: "memory")

// ============================================================================
// Prep: fp32 -> bf16 hi/lo split into a staging area chosen by `which`:
// which=0 -> (g_Ch, g_Cl)   [weights for GEMMs 1-3; ctx dead then]
// which=1 -> (g_Kh, g_Kl)   [w_o for GEMM 4; K dead after attention]
// ============================================================================
__global__ void cvt_hilo(const float* __restrict__ s, int which, int n4)
{
    __nv_bfloat16* h = which ? g_Kh : g_Ch;
    __nv_bfloat16* l = which ? g_Kl : g_Cl;
    for (int i = blockIdx.x * blockDim.x + threadIdx.x; i < n4;
         i += gridDim.x * blockDim.x) {
        const float4 x = ((const float4*)s)[i];
        uint32_t h0, l0, h1, l1;
        hilo2(x.x, x.y, h0, l0);
        hilo2(x.z, x.w, h1, l1);
        ((uint2*)h)[i] = make_uint2(h0, h1);
        ((uint2*)l)[i] = make_uint2(l0, l1);
    }
}

// ============================================================================
// GEMM: out[m,n] = sum_k A[m,k]*W[n,k] + bias[n]  (M=4096, N=1024, K=1024)
// W: pre-converted bf16 hi/lo from staging, 2-stage cp.async (no math).
//    modes 1/2/3: staging = g_Ch/g_Cl. mode 0: staging = g_Kh/g_Kl.
// A: modes 1/2/3 = fp32 input, inline hi/lo convert w/ register prefetch;
//    mode 0 = pre-converted ctx (g_Ch/g_Cl), raw LDG->STS.
// CTA 128x128, K-chunk 32, 48KB static smem (A 16K | W 16K x2).
// Smem row: 128B = 8x16B chunks (0-3 hi, 4-7 lo), swizzle c ^ (r&7).
// ============================================================================
__global__ __launch_bounds__(256) void gemm_tc(
    const float* __restrict__ A, const float* __restrict__ bias,
    float* __restrict__ C, int mode)
{
    __shared__ uint32_t sg[12288];   // A 4096w | W st0 4096w | W st1 4096w
    const uint32_t sbase = smem_u32(sg);

    const int tid = threadIdx.x;
    const int wid = tid >> 5, lane = tid & 31;
    const int g = lane >> 2, tg = lane & 3;
    const int wm = wid & 3, wn = wid >> 2;
    const int m0 = blockIdx.y * 128, n0 = blockIdx.x * 128;

    const __nv_bfloat16* WhP = (mode == 0) ? g_Kh : g_Ch;
    const __nv_bfloat16* WlP = (mode == 0) ? g_Kl : g_Cl;

    // ---- W loader: 4 cp.async transfers per thread per chunk ----
    uint32_t wdst[4];
    const __nv_bfloat16* wsrc[4];
#pragma unroll
    for (int it = 0; it < 4; ++it) {
        const int idx = tid + it * 256;          // 0..1023
        const int r = idx >> 3, c = idx & 7;
        wdst[it] = sbase + 16384 + r * 128 + (((c ^ (r & 7)) & 7) << 4);
        wsrc[it] = ((c < 4) ? WhP : WlP) + (size_t)(n0 + r) * DM + (c & 3) * 8;
    }

    // ---- A loader: thread owns row lr, 16 cols at half*16 ----
    const int lr = tid >> 1, half = tid & 1;
    const int rsw = lr & 7;
    const uint32_t stA0 = lr * 128 + (((half * 2)     ^ rsw) << 4);
    const uint32_t stA1 = lr * 128 + (((half * 2 + 1) ^ rsw) << 4);
    const uint32_t stA2 = lr * 128 + (((half * 2 + 4) ^ rsw) << 4);
    const uint32_t stA3 = lr * 128 + (((half * 2 + 5) ^ rsw) << 4);

    const float* pA = nullptr;
    const uint4 *pCh = nullptr, *pCl = nullptr;
    if (mode != 0) {
        pA = A + (size_t)(m0 + lr) * DM + half * 16;
    } else {
        pCh = (const uint4*)((const char*)g_Ch + (size_t)(m0 + lr) * (DM * 2) + half * 32);
        pCl = (const uint4*)((const char*)g_Cl + (size_t)(m0 + lr) * (DM * 2) + half * 32);
    }

    // staged A regs
    float4 a4[4];
    uint4 hv[2], lv[2];
    if (mode != 0) {
#pragma unroll
        for (int j = 0; j < 4; ++j) a4[j] = *(const float4*)(pA + j * 4);
    } else {
        hv[0] = pCh[0]; hv[1] = pCh[1]; lv[0] = pCl[0]; lv[1] = pCl[1];
    }

    // prologue: issue W chunk 0 into stage 0
#pragma unroll
    for (int it = 0; it < 4; ++it) CPA16(wdst[it], wsrc[it]);
    CPA_COMMIT();

    float acc[16][4];
#pragma unroll
    for (int t = 0; t < 16; ++t)
#pragma unroll
        for (int i = 0; i < 4; ++i) acc[t][i] = 0.f;

    char* sb = (char*)sg;

#pragma unroll 1
    for (int kc = 0; kc < 32; ++kc) {
        // STS A (convert if fp32 source)
        if (mode != 0) {
            uint4 hi0, hi1, lo0, lo1;
            hilo2(a4[0].x, a4[0].y, hi0.x, lo0.x); hilo2(a4[0].z, a4[0].w, hi0.y, lo0.y);
            hilo2(a4[1].x, a4[1].y, hi0.z, lo0.z); hilo2(a4[1].z, a4[1].w, hi0.w, lo0.w);
            hilo2(a4[2].x, a4[2].y, hi1.x, lo1.x); hilo2(a4[2].z, a4[2].w, hi1.y, lo1.y);
            hilo2(a4[3].x, a4[3].y, hi1.z, lo1.z); hilo2(a4[3].z, a4[3].w, hi1.w, lo1.w);
            *(uint4*)(sb + stA0) = hi0; *(uint4*)(sb + stA1) = hi1;
            *(uint4*)(sb + stA2) = lo0; *(uint4*)(sb + stA3) = lo1;
        } else {
            *(uint4*)(sb + stA0) = hv[0]; *(uint4*)(sb + stA1) = hv[1];
            *(uint4*)(sb + stA2) = lv[0]; *(uint4*)(sb + stA3) = lv[1];
        }

        // next W chunk + wait for current
        if (kc < 31) {
            const uint32_t so = ((kc + 1) & 1) ? 16384u : 0u;
            const int ko = (kc + 1) * 32;
#pragma unroll
            for (int it = 0; it < 4; ++it) CPA16(wdst[it] + so, wsrc[it] + ko);
            CPA_COMMIT();
            CPA_WAIT1();
        } else {
            CPA_WAIT0();
        }
        __syncthreads();

        // prefetch next A chunk into regs (overlaps MMA)
        if (kc < 31) {
            if (mode != 0) {
                const int ko = (kc + 1) * 32;
#pragma unroll
                for (int j = 0; j < 4; ++j) a4[j] = *(const float4*)(pA + ko + j * 4);
            } else {
                const int ko = (kc + 1) * 4;
                hv[0] = pCh[ko]; hv[1] = pCh[ko + 1];
                lv[0] = pCl[ko]; lv[1] = pCl[ko + 1];
            }
        }

        const uint32_t* sA = sg;
        const uint32_t* sW = sg + 4096 + (kc & 1) * 4096;
#pragma unroll
        for (int ks = 0; ks < 2; ++ks) {
            const int oH0 = (((2 * ks)     ^ g) << 2) + tg;
            const int oH1 = (((2 * ks + 1) ^ g) << 2) + tg;
            const int oL0 = (((2 * ks + 4) ^ g) << 2) + tg;
            const int oL1 = (((2 * ks + 5) ^ g) << 2) + tg;
            uint32_t ah[2][4], al[2][4];
#pragma unroll
            for (int mt = 0; mt < 2; ++mt) {
                const int rb = (wm * 32 + mt * 16 + g) * 32;
                ah[mt][0] = sA[rb + oH0];       ah[mt][1] = sA[rb + 256 + oH0];
                ah[mt][2] = sA[rb + oH1];       ah[mt][3] = sA[rb + 256 + oH1];
                al[mt][0] = sA[rb + oL0];       al[mt][1] = sA[rb + 256 + oL0];
                al[mt][2] = sA[rb + oL1];       al[mt][3] = sA[rb + 256 + oL1];
            }
#pragma unroll
            for (int nt = 0; nt < 8; ++nt) {
                const int rb = (wn * 64 + nt * 8 + g) * 32;
                uint32_t bh[2] = { sW[rb + oH0], sW[rb + oH1] };
                uint32_t bl[2] = { sW[rb + oL0], sW[rb + oL1] };
#pragma unroll
                for (int mt = 0; mt < 2; ++mt) {
                    float* d = acc[mt * 8 + nt];
                    mma_bf16(d, ah[mt], bh);
                    mma_bf16(d, ah[mt], bl);
                    mma_bf16(d, al[mt], bh);
                }
            }
        }
        __syncthreads();
    }

    // Epilogue: acc c0=(g,2tg) c1=(g,2tg+1) c2=(g+8,2tg) c3=(g+8,2tg+1)
#pragma unroll
    for (int mt = 0; mt < 2; ++mt) {
        const int rr0 = m0 + wm * 32 + mt * 16 + g;
        const int rr1 = rr0 + 8;
        const int b0_ = rr0 >> 11, s0_ = rr0 & 2047;
        const int b1_ = rr1 >> 11, s1_ = rr1 & 2047;
#pragma unroll
        for (int nt = 0; nt < 8; ++nt) {
            const float* d = acc[mt * 8 + nt];
            const int col = n0 + wn * 64 + nt * 8 + 2 * tg;
            const float bv0 = bias[col], bv1 = bias[col + 1];
            const float v0 = d[0] + bv0, v1 = d[1] + bv1;
            const float v2 = d[2] + bv0, v3 = d[3] + bv1;
            if (mode == 0) {
                *(float2*)(C + (size_t)rr0 * DM + col) = make_float2(v0, v1);
                *(float2*)(C + (size_t)rr1 * DM + col) = make_float2(v2, v3);
            } else if (mode == 3) {
                const int hh = col >> 6, dk = col & 63;
                const size_t base0 = ((size_t)(b0_ * HH + hh) * DK + dk) * SS;
                const size_t base1 = ((size_t)(b1_ * HH + hh) * DK + dk) * SS;
                store_hilo(g_Vth, g_Vtl, base0 + s0_, v0);
                store_hilo(g_Vth, g_Vtl, base0 + SS + s0_, v1);
                store_hilo(g_Vth, g_Vtl, base1 + s1_, v2);
                store_hilo(g_Vth, g_Vtl, base1 + SS + s1_, v3);
            } else {
                const int hh = col >> 6, dk = col & 63;
                __nv_bfloat16* dh = (mode == 1) ? g_Qh : g_Kh;
                __nv_bfloat16* dl = (mode == 1) ? g_Ql : g_Kl;
                uint32_t hw, lw;
                const size_t w0 = ((((size_t)(b0_ * HH + hh)) * SS + s0_) * DK + dk) >> 1;
                const size_t w1 = ((((size_t)(b1_ * HH + hh)) * SS + s1_) * DK + dk) >> 1;
                hilo2(v0, v1, hw, lw);
                ((uint32_t*)dh)[w0] = hw; ((uint32_t*)dl)[w0] = lw;
                hilo2(v2, v3, hw, lw);
                ((uint32_t*)dh)[w1] = hw; ((uint32_t*)dl)[w1] = lw;
            }
        }
    }
}

// ============================================================================
// Flash attention (R8-proven; ctx epilogue -> bf16 hi/lo).
// ============================================================================
__global__ __launch_bounds__(256) void attn_tc()
{
    __shared__ uint32_t sm[8192];            // 2 stages x (Kh|Kl|Vh|Vl 1K words)
    const uint32_t sbase = smem_u32(sm);

    const int tid = threadIdx.x;
    const int wid = tid >> 5, lane = tid & 31;
    const int g = lane >> 2, tg = lane & 3;
    const int qt = blockIdx.x, h = blockIdx.y, b = blockIdx.z;

    const size_t bh = (size_t)(b * HH + h) * SS * DK;
    const size_t bhv = (size_t)(b * HH + h) * DK * SS;
    const int q0 = qt * 128 + wid * 16;

    const int kr = tid >> 3, kcc = tid & 7;
    const uint32_t dK = sbase + kr * 128 + (((kcc ^ (kr & 7)) & 7) << 4);
    const __nv_bfloat16* pKh = g_Kh + bh + (size_t)kr * DK + kcc * 8;
    const __nv_bfloat16* pKl = g_Kl + bh + (size_t)kr * DK + kcc * 8;
    const int vr = tid >> 2, vcc = tid & 3;
    const uint32_t dV = sbase + 8192 + vr * 64 + (((vcc ^ ((vr >> 1) & 3)) & 3) << 4);
    const __nv_bfloat16* pVh = g_Vth + bhv + (size_t)vr * SS + vcc * 8;
    const __nv_bfloat16* pVl = g_Vtl + bhv + (size_t)vr * SS + vcc * 8;

    const uint32_t* Qh32 = (const uint32_t*)(g_Qh + bh);
    const uint32_t* Ql32 = (const uint32_t*)(g_Ql + bh);
    uint32_t qh[4][4], ql[4][4];
#pragma unroll
    for (int ks = 0; ks < 4; ++ks) {
        const int c0 = ks * 8 + tg;
        qh[ks][0] = Qh32[(q0 + g) * 32 + c0];
        qh[ks][1] = Qh32[(q0 + g + 8) * 32 + c0];
        qh[ks][2] = Qh32[(q0 + g) * 32 + c0 + 4];
        qh[ks][3] = Qh32[(q0 + g + 8) * 32 + c0 + 4];
        ql[ks][0] = Ql32[(q0 + g) * 32 + c0];
        ql[ks][1] = Ql32[(q0 + g + 8) * 32 + c0];
        ql[ks][2] = Ql32[(q0 + g) * 32 + c0 + 4];
        ql[ks][3] = Ql32[(q0 + g + 8) * 32 + c0 + 4];
    }

    float O[8][4];
#pragma unroll
    for (int nt = 0; nt < 8; ++nt)
#pragma unroll
        for (int i = 0; i < 4; ++i) O[nt][i] = 0.f;
    float m0r = -1e30f, m1r = -1e30f, l0r = 0.f, l1r = 0.f;
    const float scale = 0.125f;

    const int sv = (g >> 1) & 3;

    CPA16(dK, pKh); CPA16(dK + 4096, pKl);
    CPA16(dV, pVh); CPA16(dV + 4096, pVl);
    CPA_COMMIT();

    for (int kt = 0; kt < 64; ++kt) {
        if (kt < 63) {
            const uint32_t so = ((kt + 1) & 1) ? 16384u : 0u;
            const size_t koK = (size_t)(kt + 1) * 32 * DK;
            const int koV = (kt + 1) * 32;
            CPA16(dK + so, pKh + koK); CPA16(dK + so + 4096, pKl + koK);
            CPA16(dV + so, pVh + koV); CPA16(dV + so + 4096, pVl + koV);
            CPA_COMMIT();
            CPA_WAIT1();
        } else {
            CPA_WAIT0();
        }
        __syncthreads();

        const uint32_t* sKh = sm + (kt & 1) * 4096;
        const uint32_t* sKl = sKh + 1024;
        const uint32_t* sVh = sKh + 2048;
        const uint32_t* sVl = sKh + 3072;

        float S[4][4];
#pragma unroll
        for (int nt = 0; nt < 4; ++nt)
#pragma unroll
            for (int i = 0; i < 4; ++i) S[nt][i] = 0.f;
#pragma unroll
        for (int ks = 0; ks < 4; ++ks) {
            const int o0 = ((((2 * ks) ^ g) & 7) << 2) + tg;
            const int o1 = ((((2 * ks + 1) ^ g) & 7) << 2) + tg;
#pragma unroll
            for (int nt = 0; nt < 4; ++nt) {
                const int rb = (nt * 8 + g) * 32;
                uint32_t bhf[2] = { sKh[rb + o0], sKh[rb + o1] };
                uint32_t blf[2] = { sKl[rb + o0], sKl[rb + o1] };
                mma_bf16(S[nt], qh[ks], bhf);
                mma_bf16(S[nt], qh[ks], blf);
                mma_bf16(S[nt], ql[ks], bhf);
            }
        }

        float mx0 = m0r, mx1 = m1r;
#pragma unroll
        for (int nt = 0; nt < 4; ++nt) {
            mx0 = fmaxf(mx0, fmaxf(S[nt][0], S[nt][1]));
            mx1 = fmaxf(mx1, fmaxf(S[nt][2], S[nt][3]));
        }
        mx0 = fmaxf(mx0, __shfl_xor_sync(0xFFFFFFFFu, mx0, 1));
        mx0 = fmaxf(mx0, __shfl_xor_sync(0xFFFFFFFFu, mx0, 2));
        mx1 = fmaxf(mx1, __shfl_xor_sync(0xFFFFFFFFu, mx1, 1));
        mx1 = fmaxf(mx1, __shfl_xor_sync(0xFFFFFFFFu, mx1, 2));
        const float corr0 = __expf(scale * (m0r - mx0));
        const float corr1 = __expf(scale * (m1r - mx1));
        m0r = mx0; m1r = mx1;

        float sum0 = 0.f, sum1 = 0.f;
        uint32_t ph0[4], pl0[4], ph1[4], pl1[4];
#pragma unroll
        for (int nt = 0; nt < 4; ++nt) {
            const float p0 = __expf(scale * (S[nt][0] - mx0));
            const float p1 = __expf(scale * (S[nt][1] - mx0));
            const float p2 = __expf(scale * (S[nt][2] - mx1));
            const float p3 = __expf(scale * (S[nt][3] - mx1));
            sum0 += p0 + p1; sum1 += p2 + p3;
            hilo2(p0, p1, ph0[nt], pl0[nt]);
            hilo2(p2, p3, ph1[nt], pl1[nt]);
        }
        sum0 += __shfl_xor_sync(0xFFFFFFFFu, sum0, 1);
        sum0 += __shfl_xor_sync(0xFFFFFFFFu, sum0, 2);
        sum1 += __shfl_xor_sync(0xFFFFFFFFu, sum1, 1);
        sum1 += __shfl_xor_sync(0xFFFFFFFFu, sum1, 2);
        l0r = l0r * corr0 + sum0;
        l1r = l1r * corr1 + sum1;
#pragma unroll
        for (int nt = 0; nt < 8; ++nt) {
            O[nt][0] *= corr0; O[nt][1] *= corr0;
            O[nt][2] *= corr1; O[nt][3] *= corr1;
        }

#pragma unroll
        for (int kk = 0; kk < 2; ++kk) {
            const int o0 = ((((2 * kk) ^ sv) & 3) << 2) + tg;
            const int o1 = ((((2 * kk + 1) ^ sv) & 3) << 2) + tg;
            uint32_t ah[4] = { ph0[2 * kk], ph1[2 * kk], ph0[2 * kk + 1], ph1[2 * kk + 1] };
            uint32_t al[4] = { pl0[2 * kk], pl1[2 * kk], pl0[2 * kk + 1], pl1[2 * kk + 1] };
#pragma unroll
            for (int nt = 0; nt < 8; ++nt) {
                const int rb = (nt * 8 + g) * 16;
                uint32_t bhf[2] = { sVh[rb + o0], sVh[rb + o1] };
                uint32_t blf[2] = { sVl[rb + o0], sVl[rb + o1] };
                mma_bf16(O[nt], ah, bhf);
                mma_bf16(O[nt], ah, blf);
                mma_bf16(O[nt], al, bhf);
            }
        }
        __syncthreads();
    }

    // Epilogue -> ctx bf16 hi/lo (overwrites the dead weight staging)
    const float inv0 = 1.f / l0r, inv1 = 1.f / l1r;
    const int r0 = q0 + g, r1 = q0 + g + 8;
    uint32_t* ch = (uint32_t*)g_Ch;
    uint32_t* cl = (uint32_t*)g_Cl;
    const size_t base0 = (((size_t)(b * SS + r0)) * DM + h * DK) >> 1;
    const size_t base1 = (((size_t)(b * SS + r1)) * DM + h * DK) >> 1;
#pragma unroll
    for (int nt = 0; nt < 8; ++nt) {
        const int w = nt * 4 + tg;
        uint32_t hw, lw;
        hilo2(O[nt][0] * inv0, O[nt][1] * inv0, hw, lw);
        ch[base0 + w] = hw; cl[base0 + w] = lw;
        hilo2(O[nt][2] * inv1, O[nt][3] * inv1, hw, lw);
        ch[base1 + w] = hw; cl[base1 + w] = lw;
    }
}

// ----------------------------------------------------------------------------
// kernel_launch: kernel launches ONLY.
// Weight staging liveness: w_q/w_k/w_v -> g_Ch/g_Cl (ctx dead until attn);
// w_o -> g_Kh/g_Kl (K dead after attn). Stream order makes each safe.
// ----------------------------------------------------------------------------
extern "C" void kernel_launch(void* const* d_in, const int* in_sizes, int n_in,
                              void* d_out, int out_size)
{
    const float* q   = (const float*)d_in[0];
    const float* k   = (const float*)d_in[1];
    const float* v   = (const float*)d_in[2];
    const float* w_q = (const float*)d_in[3];
    const float* b_q = (const float*)d_in[4];
    const float* w_k = (const float*)d_in[5];
    const float* b_k = (const float*)d_in[6];
    const float* w_v = (const float*)d_in[7];
    const float* b_v = (const float*)d_in[8];
    const float* w_o = (const float*)d_in[9];
    const float* b_o = (const float*)d_in[10];

    dim3 gblk(256);
    dim3 ggrid(DM / 128, NTOK / 128);   // 8 x 32

    cvt_hilo<<<512, 256>>>(w_q, 0, DM * DM / 4);
    gemm_tc<<<ggrid, gblk>>>(q, b_q, nullptr, 1);

    cvt_hilo<<<512, 256>>>(w_k, 0, DM * DM / 4);
    gemm_tc<<<ggrid, gblk>>>(k, b_k, nullptr, 2);

    cvt_hilo<<<512, 256>>>(w_v, 0, DM * DM / 4);
    gemm_tc<<<ggrid, gblk>>>(v, b_v, nullptr, 3);

    attn_tc<<<dim3(SS / 128, HH, BB), 256>>>();

    cvt_hilo<<<512, 256>>>(w_o, 1, DM * DM / 4);
    gemm_tc<<<ggrid, gblk>>>(nullptr, b_o, (float*)d_out, 0);
}

// round 13
// speedup vs baseline: 3.1211x; 1.0124x over previous
#include <cuda_runtime.h>
#include <cuda_bf16.h>
#include <cstdint>

// Problem constants (fixed: B=2, S=2048, D=1024, H=16, Dk=64)
#define BB 2
#define SS 2048
#define DM 1024
#define HH 16
#define DK 64
#define NTOK (BB * SS)          // 4096 rows
#define NEL  (NTOK * DM)        // 4,194,304

// ---------------- static device scratch: 64 MB total (proven-safe) --------
__device__ __nv_bfloat16 g_Qh[NEL], g_Ql[NEL];
__device__ __nv_bfloat16 g_Kh[NEL], g_Kl[NEL];   // also w_o staging (GEMM 4)
__device__ __nv_bfloat16 g_Vth[NEL], g_Vtl[NEL];
// ctx [B,S,DM] bf16 hi/lo; first 3*DM*DM elems double as staging for
// converted w_q/w_k/w_v while ctx is dead (before attention).
__device__ __nv_bfloat16 g_Ch[NEL], g_Cl[NEL];

// ---------------- helpers ----------------
__device__ __forceinline__ uint32_t smem_u32(const void* p) {
    uint32_t a;
    asm("{ .reg .u64 t; cvta.to.shared.u64 t, %1; cvt.u32.u64 %0, t; }"
        : "=r"(a) : "l"(p));
    return a;
}

__device__ __forceinline__ void mma_bf16(float* d, const uint32_t* a, const uint32_t* b) {
    asm volatile(
        "mma.sync.aligned.m16n8k16.row.col.f32.bf16.bf16.f32 "
        "{%0,%1,%2,%3}, {%4,%5,%6,%7}, {%8,%9}, {%0,%1,%2,%3};"
        : "+f"(d[0]), "+f"(d[1]), "+f"(d[2]), "+f"(d[3])
        : "r"(a[0]), "r"(a[1]), "r"(a[2]), "r"(a[3]), "r"(b[0]), "r"(b[1]));
}

__device__ __forceinline__ void hilo2(float x, float y, uint32_t& hi, uint32_t& lo) {
    __nv_bfloat16 hx = __float2bfloat16(x);
    __nv_bfloat16 hy = __float2bfloat16(y);
    __nv_bfloat162 hp(hx, hy);
    hi = *reinterpret_cast<uint32_t*>(&hp);
    __nv_bfloat16 lx = __float2bfloat16(x - __bfloat162float(hx));
    __nv_bfloat16 ly = __float2bfloat16(y - __bfloat162float(hy));
    __nv_bfloat162 lp(lx, ly);
    lo = *reinterpret_cast<uint32_t*>(&lp);
}

__device__ __forceinline__ void store_hilo(__nv_bfloat16* h, __nv_bfloat16* l,
                                           size_t idx, float v) {
    __nv_bfloat16 hb = __float2bfloat16(v);
    h[idx] = hb;
    l[idx] = __float2bfloat16(v - __bfloat162float(hb));
}

#define CPA16(dst, src) \
    asm volatile("cp.async.cg.shared.global [%0], [%1], 16;" \
                 :: "r"(dst), "l"(src) : "memory")
#define CPA_COMMIT() asm volatile("cp.async.commit_group;" ::: "memory")
#define CPA_WAIT0()  asm volatile("cp.async.wait_group 0;" ::: "memory")
#define CPA_WAIT1()  asm volatile("cp.async.wait_group 1;" ::: "memory")

// ============================================================================
// cvt3: fp32 weights -> bf16 hi/lo staging.
// which=0: w0,w1,w2 -> g_Ch/g_Cl at element offsets 0, DM*DM, 2*DM*DM.
// which=1: w0 -> g_Kh/g_Kl at offset 0.
// ============================================================================
__global__ void cvt3(const float* __restrict__ w0, const float* __restrict__ w1,
                     const float* __restrict__ w2, int which)
{
    const int N4 = DM * DM / 4;
    const int total = which ? N4 : 3 * N4;
    __nv_bfloat16* h = which ? g_Kh : g_Ch;
    __nv_bfloat16* l = which ? g_Kl : g_Cl;
    for (int i = blockIdx.x * blockDim.x + threadIdx.x; i < total;
         i += gridDim.x * blockDim.x) {
        const float* s; int j;
        if (i < N4)            { s = w0; j = i; }
        else if (i < 2 * N4)   { s = w1; j = i - N4; }
        else                   { s = w2; j = i - 2 * N4; }
        const float4 x = ((const float4*)s)[j];
        uint32_t h0, l0, h1, l1;
        hilo2(x.x, x.y, h0, l0);
        hilo2(x.z, x.w, h1, l1);
        ((uint2*)h)[i] = make_uint2(h0, h1);
        ((uint2*)l)[i] = make_uint2(l0, l1);
    }
}

// ============================================================================
// GEMM (R10-proven pipeline): out[m,n] = sum_k A[m,k]*W[n,k] + bias[n]
// M=4096, N=1024, K=1024. CTA 128x128, K-chunk 32, 48KB static smem
// (A single stage 16KB | W double-buffered 2x16KB). Two syncs per chunk.
// mode 1: merged projections, blockIdx.z in {0,1,2} = Q/K/V. W staged in
//         g_Ch/g_Cl at z*DM*DM; A = q/k/v fp32 (inline hi/lo convert).
// mode 0: final projection. A = preconverted ctx (g_Ch/g_Cl); W staged in
//         g_Kh/g_Kl; bias in bq slot; C fp32 out.
// Smem row: 128B = 8x16B chunks (0-3 hi, 4-7 lo), swizzle c ^ (r&7).
// ============================================================================
__global__ __launch_bounds__(256) void gemm_tc(
    const float* __restrict__ q, const float* __restrict__ k,
    const float* __restrict__ v,
    const float* __restrict__ bq, const float* __restrict__ bk,
    const float* __restrict__ bv,
    float* __restrict__ C, int mode)
{
    __shared__ uint32_t sg[12288];   // A 4096w | W st0 4096w | W st1 4096w
    const uint32_t sbase = smem_u32(sg);

    const int tid = threadIdx.x;
    const int wid = tid >> 5, lane = tid & 31;
    const int g = lane >> 2, tg = lane & 3;
    const int wm = wid & 3, wn = wid >> 2;
    const int m0 = blockIdx.y * 128, n0 = blockIdx.x * 128;
    const int z = blockIdx.z;

    const float* A;
    const float* bias;
    const __nv_bfloat16 *WhP, *WlP;
    if (mode == 1) {
        A    = (z == 0) ? q : (z == 1) ? k : v;
        bias = (z == 0) ? bq : (z == 1) ? bk : bv;
        WhP  = g_Ch + (size_t)z * DM * DM;
        WlP  = g_Cl + (size_t)z * DM * DM;
    } else {
        A = nullptr; bias = bq;
        WhP = g_Kh; WlP = g_Kl;
    }

    // ---- W loader: 4 cp.async transfers per thread per chunk (R10) ----
    uint32_t wdst[4];
    const __nv_bfloat16* wsrc[4];
#pragma unroll
    for (int it = 0; it < 4; ++it) {
        const int idx = tid + it * 256;          // 0..1023
        const int r = idx >> 3, c = idx & 7;
        wdst[it] = sbase + 16384 + r * 128 + (((c ^ (r & 7)) & 7) << 4);
        wsrc[it] = ((c < 4) ? WhP : WlP) + (size_t)(n0 + r) * DM + (c & 3) * 8;
    }

    // ---- A loader: thread owns row lr, 16 cols at half*16 ----
    const int lr = tid >> 1, half = tid & 1;
    const int rsw = lr & 7;
    const uint32_t stA0 = lr * 128 + (((half * 2)     ^ rsw) << 4);
    const uint32_t stA1 = lr * 128 + (((half * 2 + 1) ^ rsw) << 4);
    const uint32_t stA2 = lr * 128 + (((half * 2 + 4) ^ rsw) << 4);
    const uint32_t stA3 = lr * 128 + (((half * 2 + 5) ^ rsw) << 4);

    const float* pA = nullptr;
    const uint4 *pCh = nullptr, *pCl = nullptr;
    if (mode == 1) {
        pA = A + (size_t)(m0 + lr) * DM + half * 16;
    } else {
        // elements: row*DM + half*16; uint4 = 8 bf16, chunk stride = 4 uint4
        pCh = (const uint4*)(g_Ch + (size_t)(m0 + lr) * DM + half * 16);
        pCl = (const uint4*)(g_Cl + (size_t)(m0 + lr) * DM + half * 16);
    }

    // staged A regs for one chunk
    float4 a4[4];
    uint4 hv[2], lv[2];
    if (mode == 1) {
#pragma unroll
        for (int j = 0; j < 4; ++j) a4[j] = *(const float4*)(pA + j * 4);
    } else {
        hv[0] = pCh[0]; hv[1] = pCh[1]; lv[0] = pCl[0]; lv[1] = pCl[1];
    }

    // prologue: issue W chunk 0 into stage 0
#pragma unroll
    for (int it = 0; it < 4; ++it) CPA16(wdst[it], wsrc[it]);
    CPA_COMMIT();

    float acc[16][4];
#pragma unroll
    for (int t = 0; t < 16; ++t)
#pragma unroll
        for (int i = 0; i < 4; ++i) acc[t][i] = 0.f;

    char* sb = (char*)sg;

#pragma unroll 1
    for (int kc = 0; kc < 32; ++kc) {
        // STS A (convert if fp32 source)
        if (mode == 1) {
            uint4 hi0, hi1, lo0, lo1;
            hilo2(a4[0].x, a4[0].y, hi0.x, lo0.x); hilo2(a4[0].z, a4[0].w, hi0.y, lo0.y);
            hilo2(a4[1].x, a4[1].y, hi0.z, lo0.z); hilo2(a4[1].z, a4[1].w, hi0.w, lo0.w);
            hilo2(a4[2].x, a4[2].y, hi1.x, lo1.x); hilo2(a4[2].z, a4[2].w, hi1.y, lo1.y);
            hilo2(a4[3].x, a4[3].y, hi1.z, lo1.z); hilo2(a4[3].z, a4[3].w, hi1.w, lo1.w);
            *(uint4*)(sb + stA0) = hi0; *(uint4*)(sb + stA1) = hi1;
            *(uint4*)(sb + stA2) = lo0; *(uint4*)(sb + stA3) = lo1;
        } else {
            *(uint4*)(sb + stA0) = hv[0]; *(uint4*)(sb + stA1) = hv[1];
            *(uint4*)(sb + stA2) = lv[0]; *(uint4*)(sb + stA3) = lv[1];
        }

        // next W chunk + wait for current
        if (kc < 31) {
            const uint32_t so = ((kc + 1) & 1) ? 16384u : 0u;
            const int ko = (kc + 1) * 32;
#pragma unroll
            for (int it = 0; it < 4; ++it) CPA16(wdst[it] + so, wsrc[it] + ko);
            CPA_COMMIT();
            CPA_WAIT1();
        } else {
            CPA_WAIT0();
        }
        __syncthreads();

        // prefetch next A chunk into regs (overlaps MMA)
        if (kc < 31) {
            if (mode == 1) {
                const int ko = (kc + 1) * 32;
#pragma unroll
                for (int j = 0; j < 4; ++j) a4[j] = *(const float4*)(pA + ko + j * 4);
            } else {
                const int ko = (kc + 1) * 4;   // 32 elements = 4 uint4
                hv[0] = pCh[ko]; hv[1] = pCh[ko + 1];
                lv[0] = pCl[ko]; lv[1] = pCl[ko + 1];
            }
        }

        const uint32_t* sA = sg;
        const uint32_t* sW = sg + 4096 + (kc & 1) * 4096;
#pragma unroll
        for (int ks = 0; ks < 2; ++ks) {
            const int oH0 = (((2 * ks)     ^ g) << 2) + tg;
            const int oH1 = (((2 * ks + 1) ^ g) << 2) + tg;
            const int oL0 = (((2 * ks + 4) ^ g) << 2) + tg;
            const int oL1 = (((2 * ks + 5) ^ g) << 2) + tg;
            uint32_t ah[2][4], al[2][4];
#pragma unroll
            for (int mt = 0; mt < 2; ++mt) {
                const int rb = (wm * 32 + mt * 16 + g) * 32;
                ah[mt][0] = sA[rb + oH0];       ah[mt][1] = sA[rb + 256 + oH0];
                ah[mt][2] = sA[rb + oH1];       ah[mt][3] = sA[rb + 256 + oH1];
                al[mt][0] = sA[rb + oL0];       al[mt][1] = sA[rb + 256 + oL0];
                al[mt][2] = sA[rb + oL1];       al[mt][3] = sA[rb + 256 + oL1];
            }
#pragma unroll
            for (int nt = 0; nt < 8; ++nt) {
                const int rb = (wn * 64 + nt * 8 + g) * 32;
                uint32_t bh[2] = { sW[rb + oH0], sW[rb + oH1] };
                uint32_t bl[2] = { sW[rb + oL0], sW[rb + oL1] };
#pragma unroll
                for (int mt = 0; mt < 2; ++mt) {
                    float* d = acc[mt * 8 + nt];
                    mma_bf16(d, ah[mt], bh);
                    mma_bf16(d, ah[mt], bl);
                    mma_bf16(d, al[mt], bh);
                }
            }
        }
        __syncthreads();
    }

    // Epilogue: acc c0=(g,2tg) c1=(g,2tg+1) c2=(g+8,2tg) c3=(g+8,2tg+1)
#pragma unroll
    for (int mt = 0; mt < 2; ++mt) {
        const int rr0 = m0 + wm * 32 + mt * 16 + g;
        const int rr1 = rr0 + 8;
        const int b0_ = rr0 >> 11, s0_ = rr0 & 2047;
        const int b1_ = rr1 >> 11, s1_ = rr1 & 2047;
#pragma unroll
        for (int nt = 0; nt < 8; ++nt) {
            const float* d = acc[mt * 8 + nt];
            const int col = n0 + wn * 64 + nt * 8 + 2 * tg;
            const float bv0 = bias[col], bv1 = bias[col + 1];
            const float v0 = d[0] + bv0, v1 = d[1] + bv1;
            const float v2 = d[2] + bv0, v3 = d[3] + bv1;
            if (mode == 0) {
                *(float2*)(C + (size_t)rr0 * DM + col) = make_float2(v0, v1);
                *(float2*)(C + (size_t)rr1 * DM + col) = make_float2(v2, v3);
            } else if (z == 2) {
                const int hh = col >> 6, dk = col & 63;
                const size_t base0 = ((size_t)(b0_ * HH + hh) * DK + dk) * SS;
                const size_t base1 = ((size_t)(b1_ * HH + hh) * DK + dk) * SS;
                store_hilo(g_Vth, g_Vtl, base0 + s0_, v0);
                store_hilo(g_Vth, g_Vtl, base0 + SS + s0_, v1);
                store_hilo(g_Vth, g_Vtl, base1 + s1_, v2);
                store_hilo(g_Vth, g_Vtl, base1 + SS + s1_, v3);
            } else {
                const int hh = col >> 6, dk = col & 63;
                __nv_bfloat16* dh = (z == 0) ? g_Qh : g_Kh;
                __nv_bfloat16* dl = (z == 0) ? g_Ql : g_Kl;
                uint32_t hw, lw;
                const size_t w0 = ((((size_t)(b0_ * HH + hh)) * SS + s0_) * DK + dk) >> 1;
                const size_t w1 = ((((size_t)(b1_ * HH + hh)) * SS + s1_) * DK + dk) >> 1;
                hilo2(v0, v1, hw, lw);
                ((uint32_t*)dh)[w0] = hw; ((uint32_t*)dl)[w0] = lw;
                hilo2(v2, v3, hw, lw);
                ((uint32_t*)dh)[w1] = hw; ((uint32_t*)dl)[w1] = lw;
            }
        }
    }
}

// ============================================================================
// Flash attention (R8/R10-proven; ctx epilogue -> bf16 hi/lo).
// ============================================================================
__global__ __launch_bounds__(256) void attn_tc()
{
    __shared__ uint32_t sm[8192];
    const uint32_t sbase = smem_u32(sm);

    const int tid = threadIdx.x;
    const int wid = tid >> 5, lane = tid & 31;
    const int g = lane >> 2, tg = lane & 3;
    const int qt = blockIdx.x, h = blockIdx.y, b = blockIdx.z;

    const size_t bh = (size_t)(b * HH + h) * SS * DK;
    const size_t bhv = (size_t)(b * HH + h) * DK * SS;
    const int q0 = qt * 128 + wid * 16;

    const int kr = tid >> 3, kcc = tid & 7;
    const uint32_t dK = sbase + kr * 128 + (((kcc ^ (kr & 7)) & 7) << 4);
    const __nv_bfloat16* pKh = g_Kh + bh + (size_t)kr * DK + kcc * 8;
    const __nv_bfloat16* pKl = g_Kl + bh + (size_t)kr * DK + kcc * 8;
    const int vr = tid >> 2, vcc = tid & 3;
    const uint32_t dV = sbase + 8192 + vr * 64 + (((vcc ^ ((vr >> 1) & 3)) & 3) << 4);
    const __nv_bfloat16* pVh = g_Vth + bhv + (size_t)vr * SS + vcc * 8;
    const __nv_bfloat16* pVl = g_Vtl + bhv + (size_t)vr * SS + vcc * 8;

    const uint32_t* Qh32 = (const uint32_t*)(g_Qh + bh);
    const uint32_t* Ql32 = (const uint32_t*)(g_Ql + bh);
    uint32_t qh[4][4], ql[4][4];
#pragma unroll
    for (int ks = 0; ks < 4; ++ks) {
        const int c0 = ks * 8 + tg;
        qh[ks][0] = Qh32[(q0 + g) * 32 + c0];
        qh[ks][1] = Qh32[(q0 + g + 8) * 32 + c0];
        qh[ks][2] = Qh32[(q0 + g) * 32 + c0 + 4];
        qh[ks][3] = Qh32[(q0 + g + 8) * 32 + c0 + 4];
        ql[ks][0] = Ql32[(q0 + g) * 32 + c0];
        ql[ks][1] = Ql32[(q0 + g + 8) * 32 + c0];
        ql[ks][2] = Ql32[(q0 + g) * 32 + c0 + 4];
        ql[ks][3] = Ql32[(q0 + g + 8) * 32 + c0 + 4];
    }

    float O[8][4];
#pragma unroll
    for (int nt = 0; nt < 8; ++nt)
#pragma unroll
        for (int i = 0; i < 4; ++i) O[nt][i] = 0.f;
    float m0r = -1e30f, m1r = -1e30f, l0r = 0.f, l1r = 0.f;
    const float scale = 0.125f;
    const int sv = (g >> 1) & 3;

    CPA16(dK, pKh); CPA16(dK + 4096, pKl);
    CPA16(dV, pVh); CPA16(dV + 4096, pVl);
    CPA_COMMIT();

    for (int kt = 0; kt < 64; ++kt) {
        if (kt < 63) {
            const uint32_t so = ((kt + 1) & 1) ? 16384u : 0u;
            const size_t koK = (size_t)(kt + 1) * 32 * DK;
            const int koV = (kt + 1) * 32;
            CPA16(dK + so, pKh + koK); CPA16(dK + so + 4096, pKl + koK);
            CPA16(dV + so, pVh + koV); CPA16(dV + so + 4096, pVl + koV);
            CPA_COMMIT();
            CPA_WAIT1();
        } else {
            CPA_WAIT0();
        }
        __syncthreads();

        const uint32_t* sKh = sm + (kt & 1) * 4096;
        const uint32_t* sKl = sKh + 1024;
        const uint32_t* sVh = sKh + 2048;
        const uint32_t* sVl = sKh + 3072;

        float S[4][4];
#pragma unroll
        for (int nt = 0; nt < 4; ++nt)
#pragma unroll
            for (int i = 0; i < 4; ++i) S[nt][i] = 0.f;
#pragma unroll
        for (int ks = 0; ks < 4; ++ks) {
            const int o0 = ((((2 * ks) ^ g) & 7) << 2) + tg;
            const int o1 = ((((2 * ks + 1) ^ g) & 7) << 2) + tg;
#pragma unroll
            for (int nt = 0; nt < 4; ++nt) {
                const int rb = (nt * 8 + g) * 32;
                uint32_t bhf[2] = { sKh[rb + o0], sKh[rb + o1] };
                uint32_t blf[2] = { sKl[rb + o0], sKl[rb + o1] };
                mma_bf16(S[nt], qh[ks], bhf);
                mma_bf16(S[nt], qh[ks], blf);
                mma_bf16(S[nt], ql[ks], bhf);
            }
        }

        float mx0 = m0r, mx1 = m1r;
#pragma unroll
        for (int nt = 0; nt < 4; ++nt) {
            mx0 = fmaxf(mx0, fmaxf(S[nt][0], S[nt][1]));
            mx1 = fmaxf(mx1, fmaxf(S[nt][2], S[nt][3]));
        }
        mx0 = fmaxf(mx0, __shfl_xor_sync(0xFFFFFFFFu, mx0, 1));
        mx0 = fmaxf(mx0, __shfl_xor_sync(0xFFFFFFFFu, mx0, 2));
        mx1 = fmaxf(mx1, __shfl_xor_sync(0xFFFFFFFFu, mx1, 1));
        mx1 = fmaxf(mx1, __shfl_xor_sync(0xFFFFFFFFu, mx1, 2));
        const float corr0 = __expf(scale * (m0r - mx0));
        const float corr1 = __expf(scale * (m1r - mx1));
        m0r = mx0; m1r = mx1;

        float sum0 = 0.f, sum1 = 0.f;
        uint32_t ph0[4], pl0[4], ph1[4], pl1[4];
#pragma unroll
        for (int nt = 0; nt < 4; ++nt) {
            const float p0 = __expf(scale * (S[nt][0] - mx0));
            const float p1 = __expf(scale * (S[nt][1] - mx0));
            const float p2 = __expf(scale * (S[nt][2] - mx1));
            const float p3 = __expf(scale * (S[nt][3] - mx1));
            sum0 += p0 + p1; sum1 += p2 + p3;
            hilo2(p0, p1, ph0[nt], pl0[nt]);
            hilo2(p2, p3, ph1[nt], pl1[nt]);
        }
        sum0 += __shfl_xor_sync(0xFFFFFFFFu, sum0, 1);
        sum0 += __shfl_xor_sync(0xFFFFFFFFu, sum0, 2);
        sum1 += __shfl_xor_sync(0xFFFFFFFFu, sum1, 1);
        sum1 += __shfl_xor_sync(0xFFFFFFFFu, sum1, 2);
        l0r = l0r * corr0 + sum0;
        l1r = l1r * corr1 + sum1;
#pragma unroll
        for (int nt = 0; nt < 8; ++nt) {
            O[nt][0] *= corr0; O[nt][1] *= corr0;
            O[nt][2] *= corr1; O[nt][3] *= corr1;
        }

#pragma unroll
        for (int kk = 0; kk < 2; ++kk) {
            const int o0 = ((((2 * kk) ^ sv) & 3) << 2) + tg;
            const int o1 = ((((2 * kk + 1) ^ sv) & 3) << 2) + tg;
            uint32_t ah[4] = { ph0[2 * kk], ph1[2 * kk], ph0[2 * kk + 1], ph1[2 * kk + 1] };
            uint32_t al[4] = { pl0[2 * kk], pl1[2 * kk], pl0[2 * kk + 1], pl1[2 * kk + 1] };
#pragma unroll
            for (int nt = 0; nt < 8; ++nt) {
                const int rb = (nt * 8 + g) * 16;
                uint32_t bhf[2] = { sVh[rb + o0], sVh[rb + o1] };
                uint32_t blf[2] = { sVl[rb + o0], sVl[rb + o1] };
                mma_bf16(O[nt], ah, bhf);
                mma_bf16(O[nt], ah, blf);
                mma_bf16(O[nt], al, bhf);
            }
        }
        __syncthreads();
    }

    // Epilogue -> ctx bf16 hi/lo (overwrites the dead weight staging)
    const float inv0 = 1.f / l0r, inv1 = 1.f / l1r;
    const int r0 = q0 + g, r1 = q0 + g + 8;
    uint32_t* ch = (uint32_t*)g_Ch;
    uint32_t* cl = (uint32_t*)g_Cl;
    const size_t base0 = (((size_t)(b * SS + r0)) * DM + h * DK) >> 1;
    const size_t base1 = (((size_t)(b * SS + r1)) * DM + h * DK) >> 1;
#pragma unroll
    for (int nt = 0; nt < 8; ++nt) {
        const int w = nt * 4 + tg;
        uint32_t hw, lw;
        hilo2(O[nt][0] * inv0, O[nt][1] * inv0, hw, lw);
        ch[base0 + w] = hw; cl[base0 + w] = lw;
        hilo2(O[nt][2] * inv1, O[nt][3] * inv1, hw, lw);
        ch[base1 + w] = hw; cl[base1 + w] = lw;
    }
}

// ----------------------------------------------------------------------------
// kernel_launch: kernel launches ONLY.
// ----------------------------------------------------------------------------
extern "C" void kernel_launch(void* const* d_in, const int* in_sizes, int n_in,
                              void* d_out, int out_size)
{
    const float* q   = (const float*)d_in[0];
    const float* k   = (const float*)d_in[1];
    const float* v   = (const float*)d_in[2];
    const float* w_q = (const float*)d_in[3];
    const float* b_q = (const float*)d_in[4];
    const float* w_k = (const float*)d_in[5];
    const float* b_k = (const float*)d_in[6];
    const float* w_v = (const float*)d_in[7];
    const float* b_v = (const float*)d_in[8];
    const float* w_o = (const float*)d_in[9];
    const float* b_o = (const float*)d_in[10];

    // Stage all three projection weights, then one merged projection GEMM.
    cvt3<<<768, 256>>>(w_q, w_k, w_v, 0);
    gemm_tc<<<dim3(DM / 128, NTOK / 128, 3), 256>>>(q, k, v, b_q, b_k, b_v,
                                                    nullptr, 1);

    attn_tc<<<dim3(SS / 128, HH, BB), 256>>>();

    cvt3<<<256, 256>>>(w_o, nullptr, nullptr, 1);
    gemm_tc<<<dim3(DM / 128, NTOK / 128, 1), 256>>>(nullptr, nullptr, nullptr,
                                                    b_o, nullptr, nullptr,
                                                    (float*)d_out, 0);
}